// round 6
// baseline (speedup 1.0000x reference)
#include <cuda_runtime.h>
#include <cuda_bf16.h>
#include <cstdint>

#define BROWS 16384
#define EDIM  1024
#define STAGE_BYTES 40960          // Ahi 10240 | Alo 10240 | Bhi 10240 | Blo 10240
#define SMEM_SZ (2*STAGE_BYTES)    // 81920
#define ROWB 80                    // padded row stride in bytes (40 halves)

__device__ float g_t [(size_t)BROWS*EDIM];
__device__ float g_a [(size_t)BROWS*EDIM];
__device__ float g_tc[(size_t)BROWS*EDIM];
__device__ float g_ac[(size_t)BROWS*EDIM];
__device__ float g_wvo[(size_t)EDIM*EDIM];
__device__ float g_cv[EDIM];

static __device__ __forceinline__ uint32_t s2u(const void* p){
  uint32_t a; asm("{ .reg .u64 t; cvta.to.shared.u64 t, %1; cvt.u32.u64 %0, t; }" : "=r"(a) : "l"(p)); return a;
}

#define LDM4(r, ad) asm volatile( \
  "ldmatrix.sync.aligned.m8n8.x4.shared.b16 {%0,%1,%2,%3}, [%4];" \
  : "=r"((r)[0]),"=r"((r)[1]),"=r"((r)[2]),"=r"((r)[3]) : "r"(ad))

#define MMA(cc, aa, b0, b1) asm volatile( \
  "mma.sync.aligned.m16n8k16.row.col.f32.bf16.bf16.f32 " \
  "{%0,%1,%2,%3},{%4,%5,%6,%7},{%8,%9},{%0,%1,%2,%3};" \
  : "+f"((cc)[0]),"+f"((cc)[1]),"+f"((cc)[2]),"+f"((cc)[3]) \
  : "r"((aa)[0]),"r"((aa)[1]),"r"((aa)[2]),"r"((aa)[3]),"r"(b0),"r"(b1))

static __device__ __forceinline__ void split_store8(char* hb, char* lb, int off, float4 v){
  __nv_bfloat16 h0=__float2bfloat16(v.x), h1=__float2bfloat16(v.y);
  __nv_bfloat16 h2=__float2bfloat16(v.z), h3=__float2bfloat16(v.w);
  __nv_bfloat16 l0=__float2bfloat16(v.x-__bfloat162float(h0));
  __nv_bfloat16 l1=__float2bfloat16(v.y-__bfloat162float(h1));
  __nv_bfloat16 l2=__float2bfloat16(v.z-__bfloat162float(h2));
  __nv_bfloat16 l3=__float2bfloat16(v.w-__bfloat162float(h3));
  uint2 h, l;
  h.x=(uint32_t)__bfloat16_as_ushort(h0) | ((uint32_t)__bfloat16_as_ushort(h1)<<16);
  h.y=(uint32_t)__bfloat16_as_ushort(h2) | ((uint32_t)__bfloat16_as_ushort(h3)<<16);
  l.x=(uint32_t)__bfloat16_as_ushort(l0) | ((uint32_t)__bfloat16_as_ushort(l1)<<16);
  l.y=(uint32_t)__bfloat16_as_ushort(l2) | ((uint32_t)__bfloat16_as_ushort(l3)<<16);
  *(uint2*)(hb+off)=h; *(uint2*)(lb+off)=l;
}
static __device__ __forceinline__ void split_store2(char* hb, char* lb, int off, float v){
  __nv_bfloat16 h=__float2bfloat16(v);
  __nv_bfloat16 l=__float2bfloat16(v-__bfloat162float(h));
  *(unsigned short*)(hb+off)=__bfloat16_as_ushort(h);
  *(unsigned short*)(lb+off)=__bfloat16_as_ushort(l);
}

// C[m][n] = sum_k A[m][k] * Wlogical[n][k]  (+bias) (+gate blend epilogue)
// TRANSW: Wlogical[n][k] = W[k*ldw + n]  (for Wvo = Wo @ Wv)
// A is concat(A1[:,0:K1], A2[:,0:Ktot-K1]) along k; K1 % 32 == 0.
template<bool TRANSW, bool GATE>
__global__ void __launch_bounds__(256)
gemm_kernel(const float* __restrict__ A1, int lda1,
            const float* __restrict__ A2, int lda2, int K1,
            const float* __restrict__ W, int ldw,
            const float* __restrict__ bias,
            const float* __restrict__ gt_in, const float* __restrict__ gc_in,
            float* __restrict__ out, int ldo, int Ktot)
{
  extern __shared__ char smem[];
  const int tid = threadIdx.x, lane = tid & 31, wid = tid >> 5;
  const int mwarp = wid & 3, nwarp = wid >> 2;           // 4 x 2 warp grid
  const int m0 = blockIdx.y * 128, n0 = blockIdx.x * 128;
  const uint32_t sb = s2u(smem);

  float c[2][8][4];
  #pragma unroll
  for (int i=0;i<2;i++)
    #pragma unroll
    for (int j=0;j<8;j++)
      #pragma unroll
      for (int q=0;q<4;q++) c[i][j][q] = 0.f;

  // per-lane ldmatrix address offsets (bytes within a tile)
  const uint32_t aoff = (uint32_t)((lane&15)*ROWB + ((lane>>4)&1)*16);
  const uint32_t boff = (uint32_t)(((lane&7) + ((lane>>4)&1)*8)*ROWB + ((lane>>3)&1)*16);

  const int nk = Ktot >> 5;
  float4 ra[4]; float4 rb4[4]; float rbs[16];

  // ---- loaders ----
  #define LDG_A(kc) do { \
    int kk = (kc) << 5; \
    const float* Ap; int lda; \
    if (kk < K1){ Ap = A1 + (size_t)m0*lda1 + kk; lda = lda1; } \
    else        { Ap = A2 + (size_t)m0*lda2 + (kk - K1); lda = lda2; } \
    _Pragma("unroll") \
    for (int i=0;i<4;i++){ \
      int row = (tid>>3) + i*32, c4 = (tid&7)*4; \
      ra[i] = *(const float4*)(Ap + (size_t)row*lda + c4); \
    } \
  } while(0)

  #define LDG_B(kc) do { \
    int kk = (kc) << 5; \
    if (!TRANSW){ \
      _Pragma("unroll") \
      for (int i=0;i<4;i++){ \
        int row = (tid>>3) + i*32, c4 = (tid&7)*4; \
        rb4[i] = *(const float4*)(W + (size_t)(n0+row)*ldw + kk + c4); \
      } \
    } else { \
      _Pragma("unroll") \
      for (int i=0;i<16;i++){ \
        int e = tid + i*256; int nr = e & 127, cc2 = e >> 7; \
        rbs[i] = W[(size_t)(kk+cc2)*ldw + n0 + nr]; \
      } \
    } \
  } while(0)

  #define STS_ALL(s) do { \
    char* hA = smem + (s)*STAGE_BYTES; char* lA = hA + 10240; \
    char* hB = hA + 20480;             char* lB = hA + 30720; \
    _Pragma("unroll") \
    for (int i=0;i<4;i++){ \
      int row = (tid>>3) + i*32, c4 = (tid&7)*4; \
      split_store8(hA, lA, row*ROWB + c4*2, ra[i]); \
    } \
    if (!TRANSW){ \
      _Pragma("unroll") \
      for (int i=0;i<4;i++){ \
        int row = (tid>>3) + i*32, c4 = (tid&7)*4; \
        split_store8(hB, lB, row*ROWB + c4*2, rb4[i]); \
      } \
    } else { \
      _Pragma("unroll") \
      for (int i=0;i<16;i++){ \
        int e = tid + i*256; int nr = e & 127, cc2 = e >> 7; \
        split_store2(hB, lB, nr*ROWB + cc2*2, rbs[i]); \
      } \
    } \
  } while(0)

  // prologue
  LDG_A(0); LDG_B(0);
  STS_ALL(0);
  __syncthreads();

  for (int kc = 0; kc < nk; kc++){
    const bool hasNext = (kc + 1 < nk);
    if (hasNext){ LDG_A(kc+1); LDG_B(kc+1); }

    // compute chunk kc from stage kc&1
    {
      const uint32_t base = sb + (uint32_t)(kc&1)*STAGE_BYTES;
      #pragma unroll
      for (int ks=0; ks<2; ks++){
        uint32_t ah[2][4], al[2][4], bh[4][4], bl[4][4];
        #pragma unroll
        for (int mi=0;mi<2;mi++){
          uint32_t ad = base + (uint32_t)((mwarp*32 + mi*16)*ROWB + ks*32) + aoff;
          LDM4(ah[mi], ad);
          LDM4(al[mi], ad + 10240u);
        }
        #pragma unroll
        for (int bi=0;bi<4;bi++){
          uint32_t bd = base + 20480u + (uint32_t)((nwarp*64 + bi*16)*ROWB + ks*32) + boff;
          LDM4(bh[bi], bd);
          LDM4(bl[bi], bd + 10240u);
        }
        // hi*hi
        #pragma unroll
        for (int mi=0;mi<2;mi++)
          #pragma unroll
          for (int ni=0;ni<8;ni++)
            MMA(c[mi][ni], ah[mi], bh[ni>>1][(ni&1)*2], bh[ni>>1][(ni&1)*2+1]);
        // hi*lo
        #pragma unroll
        for (int mi=0;mi<2;mi++)
          #pragma unroll
          for (int ni=0;ni<8;ni++)
            MMA(c[mi][ni], ah[mi], bl[ni>>1][(ni&1)*2], bl[ni>>1][(ni&1)*2+1]);
        // lo*hi
        #pragma unroll
        for (int mi=0;mi<2;mi++)
          #pragma unroll
          for (int ni=0;ni<8;ni++)
            MMA(c[mi][ni], al[mi], bh[ni>>1][(ni&1)*2], bh[ni>>1][(ni&1)*2+1]);
      }
    }

    if (hasNext) STS_ALL((kc+1)&1);
    __syncthreads();
  }

  // ---- epilogue: regs -> global, fused bias (+ sigmoid gate blend) ----
  const int gid = lane >> 2, tig = lane & 3;
  #pragma unroll
  for (int mi=0;mi<2;mi++){
    const int rbase = m0 + mwarp*32 + mi*16 + gid;
    #pragma unroll
    for (int ni=0;ni<8;ni++){
      const int col = n0 + nwarp*64 + ni*8 + tig*2;
      const float b0 = bias ? bias[col] : 0.f;
      const float b1 = bias ? bias[col+1] : 0.f;
      #pragma unroll
      for (int half=0; half<2; half++){
        const int r = rbase + half*8;
        float z0 = c[mi][ni][half*2+0] + b0;
        float z1 = c[mi][ni][half*2+1] + b1;
        if (GATE){
          const float2 tv = *(const float2*)(gt_in + (size_t)r*EDIM + col);
          const float2 cv = *(const float2*)(gc_in + (size_t)r*EDIM + col);
          float g0 = 1.f/(1.f + __expf(-z0));
          float g1 = 1.f/(1.f + __expf(-z1));
          z0 = g0*tv.x + (1.f-g0)*cv.x;
          z1 = g1*tv.y + (1.f-g1)*cv.y;
        }
        float2 o; o.x = z0; o.y = z1;
        *(float2*)(out + (size_t)r*ldo + col) = o;
      }
    }
  }
  #undef LDG_A
  #undef LDG_B
  #undef STS_ALL
}

// cv = Wo @ bv + bo
__global__ void cv_kernel(const float* __restrict__ Wo, const float* __restrict__ bv,
                          const float* __restrict__ bo, float* __restrict__ cv){
  __shared__ float red[128];
  int i = blockIdx.x;
  float s = 0.f;
  for (int k = threadIdx.x; k < EDIM; k += 128) s += Wo[(size_t)i*EDIM + k] * bv[k];
  red[threadIdx.x] = s; __syncthreads();
  for (int off = 64; off; off >>= 1){
    if (threadIdx.x < off) red[threadIdx.x] += red[threadIdx.x+off];
    __syncthreads();
  }
  if (threadIdx.x == 0) cv[i] = red[0] + bo[i];
}

extern "C" void kernel_launch(void* const* d_in, const int* in_sizes, int n_in,
                              void* d_out, int out_size){
  const float* text = (const float*)d_in[0];
  const float* audio= (const float*)d_in[1];
  const float* Wt = (const float*)d_in[2];  const float* bt = (const float*)d_in[3];
  const float* Wa = (const float*)d_in[4];  const float* ba = (const float*)d_in[5];
  const float* Wv = (const float*)d_in[10]; const float* bv = (const float*)d_in[11];
  const float* Wo = (const float*)d_in[12]; const float* bo = (const float*)d_in[13];
  const float* Wgt= (const float*)d_in[14]; const float* bgt= (const float*)d_in[15];
  const float* Wga= (const float*)d_in[16]; const float* bga= (const float*)d_in[17];
  float* out = (float*)d_out;

  float *t,*a,*tc,*ac,*wvo,*cv;
  cudaGetSymbolAddress((void**)&t,  g_t);
  cudaGetSymbolAddress((void**)&a,  g_a);
  cudaGetSymbolAddress((void**)&tc, g_tc);
  cudaGetSymbolAddress((void**)&ac, g_ac);
  cudaGetSymbolAddress((void**)&wvo,g_wvo);
  cudaGetSymbolAddress((void**)&cv, g_cv);

  cudaFuncSetAttribute(gemm_kernel<false,false>, cudaFuncAttributeMaxDynamicSharedMemorySize, SMEM_SZ);
  cudaFuncSetAttribute(gemm_kernel<true ,false>, cudaFuncAttributeMaxDynamicSharedMemorySize, SMEM_SZ);
  cudaFuncSetAttribute(gemm_kernel<false,true >, cudaFuncAttributeMaxDynamicSharedMemorySize, SMEM_SZ);

  dim3 gridB(8, BROWS/128);

  cv_kernel<<<EDIM,128>>>(Wo, bv, bo, cv);
  // Wvo = Wo @ Wv  (Wlogical[n][k] = Wv[k][n] -> TRANSW)
  gemm_kernel<true ,false><<<dim3(8,8), 256, SMEM_SZ>>>(Wo,EDIM, Wo,EDIM, EDIM, Wv,EDIM, nullptr, nullptr,nullptr, wvo, EDIM, EDIM);
  // t = text @ Wt.T + bt
  gemm_kernel<false,false><<<gridB, 256, SMEM_SZ>>>(text,768, text,768, 768, Wt,768, bt, nullptr,nullptr, t, EDIM, 768);
  // a = audio @ Wa.T + ba
  gemm_kernel<false,false><<<gridB, 256, SMEM_SZ>>>(audio,EDIM, audio,EDIM, EDIM, Wa,EDIM, ba, nullptr,nullptr, a, EDIM, EDIM);
  // t_ctx = a @ Wvo.T + cv
  gemm_kernel<false,false><<<gridB, 256, SMEM_SZ>>>(a,EDIM, a,EDIM, EDIM, wvo,EDIM, cv, nullptr,nullptr, tc, EDIM, EDIM);
  // a_ctx = t @ Wvo.T + cv
  gemm_kernel<false,false><<<gridB, 256, SMEM_SZ>>>(t,EDIM, t,EDIM, EDIM, wvo,EDIM, cv, nullptr,nullptr, ac, EDIM, EDIM);
  // refined_t = gate(concat(t,t_ctx) @ Wgt.T + bgt ; t, t_ctx)
  gemm_kernel<false,true ><<<gridB, 256, SMEM_SZ>>>(t,EDIM, tc,EDIM, EDIM, Wgt,2*EDIM, bgt, t, tc, out, EDIM, 2*EDIM);
  // refined_a = gate(concat(a,a_ctx) @ Wga.T + bga ; a, a_ctx)
  gemm_kernel<false,true ><<<gridB, 256, SMEM_SZ>>>(a,EDIM, ac,EDIM, EDIM, Wga,2*EDIM, bga, a, ac, out + (size_t)BROWS*EDIM, EDIM, 2*EDIM);
}

// round 9
// speedup vs baseline: 1.0490x; 1.0490x over previous
#include <cuda_runtime.h>
#include <cuda_bf16.h>
#include <cstdint>

#define BROWS 16384
#define EDIM  1024
// Stage layout (bytes): Ahi 20480 | Alo 20480 | Bhi 10240 | Blo 10240
#define A_HI_OFF 0
#define A_LO_OFF 20480
#define B_HI_OFF 40960
#define B_LO_OFF 51200
#define STAGE_BYTES 61440
#define SMEM_SZ (2*STAGE_BYTES)    // 122880
#define ROWB 80                    // padded row stride in bytes (40 halves)

__device__ float g_t [(size_t)BROWS*EDIM];
__device__ float g_a [(size_t)BROWS*EDIM];
__device__ float g_tc[(size_t)BROWS*EDIM];
__device__ float g_ac[(size_t)BROWS*EDIM];
__device__ float g_wvo[(size_t)EDIM*EDIM];
__device__ float g_cv[EDIM];

static __device__ __forceinline__ uint32_t s2u(const void* p){
  uint32_t a; asm("{ .reg .u64 t; cvta.to.shared.u64 t, %1; cvt.u32.u64 %0, t; }" : "=r"(a) : "l"(p)); return a;
}

#define LDM4(r, ad) asm volatile( \
  "ldmatrix.sync.aligned.m8n8.x4.shared.b16 {%0,%1,%2,%3}, [%4];" \
  : "=r"((r)[0]),"=r"((r)[1]),"=r"((r)[2]),"=r"((r)[3]) : "r"(ad))

#define MMA(cc, aa, b0, b1) asm volatile( \
  "mma.sync.aligned.m16n8k16.row.col.f32.bf16.bf16.f32 " \
  "{%0,%1,%2,%3},{%4,%5,%6,%7},{%8,%9},{%0,%1,%2,%3};" \
  : "+f"((cc)[0]),"+f"((cc)[1]),"+f"((cc)[2]),"+f"((cc)[3]) \
  : "r"((aa)[0]),"r"((aa)[1]),"r"((aa)[2]),"r"((aa)[3]),"r"(b0),"r"(b1))

static __device__ __forceinline__ void split_store8(char* hb, char* lb, int off, float4 v){
  __nv_bfloat16 h0=__float2bfloat16(v.x), h1=__float2bfloat16(v.y);
  __nv_bfloat16 h2=__float2bfloat16(v.z), h3=__float2bfloat16(v.w);
  __nv_bfloat16 l0=__float2bfloat16(v.x-__bfloat162float(h0));
  __nv_bfloat16 l1=__float2bfloat16(v.y-__bfloat162float(h1));
  __nv_bfloat16 l2=__float2bfloat16(v.z-__bfloat162float(h2));
  __nv_bfloat16 l3=__float2bfloat16(v.w-__bfloat162float(h3));
  uint2 h, l;
  h.x=(uint32_t)__bfloat16_as_ushort(h0) | ((uint32_t)__bfloat16_as_ushort(h1)<<16);
  h.y=(uint32_t)__bfloat16_as_ushort(h2) | ((uint32_t)__bfloat16_as_ushort(h3)<<16);
  l.x=(uint32_t)__bfloat16_as_ushort(l0) | ((uint32_t)__bfloat16_as_ushort(l1)<<16);
  l.y=(uint32_t)__bfloat16_as_ushort(l2) | ((uint32_t)__bfloat16_as_ushort(l3)<<16);
  *(uint2*)(hb+off)=h; *(uint2*)(lb+off)=l;
}
static __device__ __forceinline__ void split_store2(char* hb, char* lb, int off, float v){
  __nv_bfloat16 h=__float2bfloat16(v);
  __nv_bfloat16 l=__float2bfloat16(v-__bfloat162float(h));
  *(unsigned short*)(hb+off)=__bfloat16_as_ushort(h);
  *(unsigned short*)(lb+off)=__bfloat16_as_ushort(l);
}

// C[m][n] = sum_k A[m][k] * Wlogical[n][k]  (+bias) (+gate blend epilogue)
// TRANSW: Wlogical[n][k] = W[k*ldw + n]  (for Wvo = Wo @ Wv)
// A is concat(A1[:,0:K1], A2[:,0:Ktot-K1]) along k; K1 % 32 == 0.
// CTA tile 256(M) x 128(N), K-chunk 32, 8 warps as 4x2, warp tile 64x64.
template<bool TRANSW, bool GATE>
__global__ void __launch_bounds__(256)
gemm_kernel(const float* __restrict__ A1, int lda1,
            const float* __restrict__ A2, int lda2, int K1,
            const float* __restrict__ W, int ldw,
            const float* __restrict__ bias,
            const float* __restrict__ gt_in, const float* __restrict__ gc_in,
            float* __restrict__ out, int ldo, int Ktot)
{
  extern __shared__ char smem[];
  const int tid = threadIdx.x, lane = tid & 31, wid = tid >> 5;
  const int mwarp = wid & 3, nwarp = wid >> 2;           // 4 x 2 warp grid
  const int m0 = blockIdx.y * 256, n0 = blockIdx.x * 128;
  const uint32_t sb = s2u(smem);

  float c[4][8][4];
  #pragma unroll
  for (int i=0;i<4;i++)
    #pragma unroll
    for (int j=0;j<8;j++)
      #pragma unroll
      for (int q=0;q<4;q++) c[i][j][q] = 0.f;

  // per-lane ldmatrix address offsets (bytes within a tile)
  const uint32_t aoff = (uint32_t)((lane&15)*ROWB + ((lane>>4)&1)*16);
  const uint32_t boff = (uint32_t)(((lane&7) + ((lane>>4)&1)*8)*ROWB + ((lane>>3)&1)*16);

  const int nk = Ktot >> 5;
  float4 ra[8]; float4 rb4[4]; float rbs[16];

  // ---- loaders ----
  #define LDG_A(kc) do { \
    int kk = (kc) << 5; \
    const float* Ap; int lda; \
    if (kk < K1){ Ap = A1 + (size_t)m0*lda1 + kk; lda = lda1; } \
    else        { Ap = A2 + (size_t)m0*lda2 + (kk - K1); lda = lda2; } \
    _Pragma("unroll") \
    for (int i=0;i<8;i++){ \
      int row = (tid>>3) + i*32, c4 = (tid&7)*4; \
      ra[i] = *(const float4*)(Ap + (size_t)row*lda + c4); \
    } \
  } while(0)

  #define LDG_B(kc) do { \
    int kk = (kc) << 5; \
    if (!TRANSW){ \
      _Pragma("unroll") \
      for (int i=0;i<4;i++){ \
        int row = (tid>>3) + i*32, c4 = (tid&7)*4; \
        rb4[i] = *(const float4*)(W + (size_t)(n0+row)*ldw + kk + c4); \
      } \
    } else { \
      _Pragma("unroll") \
      for (int i=0;i<16;i++){ \
        int e = tid + i*256; int nr = e & 127, cc2 = e >> 7; \
        rbs[i] = W[(size_t)(kk+cc2)*ldw + n0 + nr]; \
      } \
    } \
  } while(0)

  #define STS_ALL(s) do { \
    char* hA = smem + (s)*STAGE_BYTES + A_HI_OFF; char* lA = smem + (s)*STAGE_BYTES + A_LO_OFF; \
    char* hB = smem + (s)*STAGE_BYTES + B_HI_OFF; char* lB = smem + (s)*STAGE_BYTES + B_LO_OFF; \
    _Pragma("unroll") \
    for (int i=0;i<8;i++){ \
      int row = (tid>>3) + i*32, c4 = (tid&7)*4; \
      split_store8(hA, lA, row*ROWB + c4*2, ra[i]); \
    } \
    if (!TRANSW){ \
      _Pragma("unroll") \
      for (int i=0;i<4;i++){ \
        int row = (tid>>3) + i*32, c4 = (tid&7)*4; \
        split_store8(hB, lB, row*ROWB + c4*2, rb4[i]); \
      } \
    } else { \
      _Pragma("unroll") \
      for (int i=0;i<16;i++){ \
        int e = tid + i*256; int nr = e & 127, cc2 = e >> 7; \
        split_store2(hB, lB, nr*ROWB + cc2*2, rbs[i]); \
      } \
    } \
  } while(0)

  // prologue
  LDG_A(0); LDG_B(0);
  STS_ALL(0);
  __syncthreads();

  for (int kc = 0; kc < nk; kc++){
    const bool hasNext = (kc + 1 < nk);
    if (hasNext){ LDG_A(kc+1); LDG_B(kc+1); }

    // compute chunk kc from stage kc&1
    {
      const uint32_t base = sb + (uint32_t)(kc&1)*STAGE_BYTES;
      #pragma unroll
      for (int ks=0; ks<2; ks++){
        uint32_t ah[4][4], al[4][4], bb[4][4];
        #pragma unroll
        for (int mi=0;mi<4;mi++){
          uint32_t ad = base + (uint32_t)((mwarp*64 + mi*16)*ROWB + ks*32) + aoff;
          LDM4(ah[mi], ad);
          LDM4(al[mi], ad + (uint32_t)(A_LO_OFF - A_HI_OFF));
        }
        // B hi
        #pragma unroll
        for (int bi=0;bi<4;bi++){
          uint32_t bd = base + (uint32_t)B_HI_OFF + (uint32_t)((nwarp*64 + bi*16)*ROWB + ks*32) + boff;
          LDM4(bb[bi], bd);
        }
        // hi*hi
        #pragma unroll
        for (int mi=0;mi<4;mi++)
          #pragma unroll
          for (int ni=0;ni<8;ni++)
            MMA(c[mi][ni], ah[mi], bb[ni>>1][(ni&1)*2], bb[ni>>1][(ni&1)*2+1]);
        // lo*hi
        #pragma unroll
        for (int mi=0;mi<4;mi++)
          #pragma unroll
          for (int ni=0;ni<8;ni++)
            MMA(c[mi][ni], al[mi], bb[ni>>1][(ni&1)*2], bb[ni>>1][(ni&1)*2+1]);
        // B lo (overwrite bb)
        #pragma unroll
        for (int bi=0;bi<4;bi++){
          uint32_t bd = base + (uint32_t)B_LO_OFF + (uint32_t)((nwarp*64 + bi*16)*ROWB + ks*32) + boff;
          LDM4(bb[bi], bd);
        }
        // hi*lo
        #pragma unroll
        for (int mi=0;mi<4;mi++)
          #pragma unroll
          for (int ni=0;ni<8;ni++)
            MMA(c[mi][ni], ah[mi], bb[ni>>1][(ni&1)*2], bb[ni>>1][(ni&1)*2+1]);
      }
    }

    if (hasNext) STS_ALL((kc+1)&1);
    __syncthreads();
  }

  // ---- epilogue: regs -> global, fused bias (+ sigmoid gate blend) ----
  const int gid = lane >> 2, tig = lane & 3;
  #pragma unroll
  for (int mi=0;mi<4;mi++){
    const int rbase = m0 + mwarp*64 + mi*16 + gid;
    #pragma unroll
    for (int ni=0;ni<8;ni++){
      const int col = n0 + nwarp*64 + ni*8 + tig*2;
      const float b0 = bias ? bias[col] : 0.f;
      const float b1 = bias ? bias[col+1] : 0.f;
      #pragma unroll
      for (int half=0; half<2; half++){
        const int r = rbase + half*8;
        float z0 = c[mi][ni][half*2+0] + b0;
        float z1 = c[mi][ni][half*2+1] + b1;
        if (GATE){
          const float2 tv = *(const float2*)(gt_in + (size_t)r*EDIM + col);
          const float2 cv = *(const float2*)(gc_in + (size_t)r*EDIM + col);
          float g0 = 1.f/(1.f + __expf(-z0));
          float g1 = 1.f/(1.f + __expf(-z1));
          z0 = g0*tv.x + (1.f-g0)*cv.x;
          z1 = g1*tv.y + (1.f-g1)*cv.y;
        }
        float2 o; o.x = z0; o.y = z1;
        *(float2*)(out + (size_t)r*ldo + col) = o;
      }
    }
  }
  #undef LDG_A
  #undef LDG_B
  #undef STS_ALL
}

// cv = Wo @ bv + bo
__global__ void cv_kernel(const float* __restrict__ Wo, const float* __restrict__ bv,
                          const float* __restrict__ bo, float* __restrict__ cv){
  __shared__ float red[128];
  int i = blockIdx.x;
  float s = 0.f;
  for (int k = threadIdx.x; k < EDIM; k += 128) s += Wo[(size_t)i*EDIM + k] * bv[k];
  red[threadIdx.x] = s; __syncthreads();
  for (int off = 64; off; off >>= 1){
    if (threadIdx.x < off) red[threadIdx.x] += red[threadIdx.x+off];
    __syncthreads();
  }
  if (threadIdx.x == 0) cv[i] = red[0] + bo[i];
}

extern "C" void kernel_launch(void* const* d_in, const int* in_sizes, int n_in,
                              void* d_out, int out_size){
  const float* text = (const float*)d_in[0];
  const float* audio= (const float*)d_in[1];
  const float* Wt = (const float*)d_in[2];  const float* bt = (const float*)d_in[3];
  const float* Wa = (const float*)d_in[4];  const float* ba = (const float*)d_in[5];
  const float* Wv = (const float*)d_in[10]; const float* bv = (const float*)d_in[11];
  const float* Wo = (const float*)d_in[12]; const float* bo = (const float*)d_in[13];
  const float* Wgt= (const float*)d_in[14]; const float* bgt= (const float*)d_in[15];
  const float* Wga= (const float*)d_in[16]; const float* bga= (const float*)d_in[17];
  float* out = (float*)d_out;

  float *t,*a,*tc,*ac,*wvo,*cv;
  cudaGetSymbolAddress((void**)&t,  g_t);
  cudaGetSymbolAddress((void**)&a,  g_a);
  cudaGetSymbolAddress((void**)&tc, g_tc);
  cudaGetSymbolAddress((void**)&ac, g_ac);
  cudaGetSymbolAddress((void**)&wvo,g_wvo);
  cudaGetSymbolAddress((void**)&cv, g_cv);

  cudaFuncSetAttribute(gemm_kernel<false,false>, cudaFuncAttributeMaxDynamicSharedMemorySize, SMEM_SZ);
  cudaFuncSetAttribute(gemm_kernel<true ,false>, cudaFuncAttributeMaxDynamicSharedMemorySize, SMEM_SZ);
  cudaFuncSetAttribute(gemm_kernel<false,true >, cudaFuncAttributeMaxDynamicSharedMemorySize, SMEM_SZ);

  dim3 gridB(8, BROWS/256);   // 8 x 64 = 512 CTAs

  cv_kernel<<<EDIM,128>>>(Wo, bv, bo, cv);
  // Wvo = Wo @ Wv  (Wlogical[n][k] = Wv[k][n] -> TRANSW)
  gemm_kernel<true ,false><<<dim3(8,4), 256, SMEM_SZ>>>(Wo,EDIM, Wo,EDIM, EDIM, Wv,EDIM, nullptr, nullptr,nullptr, wvo, EDIM, EDIM);
  // t = text @ Wt.T + bt
  gemm_kernel<false,false><<<gridB, 256, SMEM_SZ>>>(text,768, text,768, 768, Wt,768, bt, nullptr,nullptr, t, EDIM, 768);
  // a = audio @ Wa.T + ba
  gemm_kernel<false,false><<<gridB, 256, SMEM_SZ>>>(audio,EDIM, audio,EDIM, EDIM, Wa,EDIM, ba, nullptr,nullptr, a, EDIM, EDIM);
  // t_ctx = a @ Wvo.T + cv
  gemm_kernel<false,false><<<gridB, 256, SMEM_SZ>>>(a,EDIM, a,EDIM, EDIM, wvo,EDIM, cv, nullptr,nullptr, tc, EDIM, EDIM);
  // a_ctx = t @ Wvo.T + cv
  gemm_kernel<false,false><<<gridB, 256, SMEM_SZ>>>(t,EDIM, t,EDIM, EDIM, wvo,EDIM, cv, nullptr,nullptr, ac, EDIM, EDIM);
  // refined_t = gate(concat(t,t_ctx) @ Wgt.T + bgt ; t, t_ctx)
  gemm_kernel<false,true ><<<gridB, 256, SMEM_SZ>>>(t,EDIM, tc,EDIM, EDIM, Wgt,2*EDIM, bgt, t, tc, out, EDIM, 2*EDIM);
  // refined_a = gate(concat(a,a_ctx) @ Wga.T + bga ; a, a_ctx)
  gemm_kernel<false,true ><<<gridB, 256, SMEM_SZ>>>(a,EDIM, ac,EDIM, EDIM, Wga,2*EDIM, bga, a, ac, out + (size_t)BROWS*EDIM, EDIM, 2*EDIM);
}

// round 11
// speedup vs baseline: 1.0703x; 1.0204x over previous
#include <cuda_runtime.h>
#include <cuda_bf16.h>
#include <cstdint>

#define BROWS 16384
#define EDIM  1024
#define TDIM  768

// GEMM smem stage layout (bytes): Ahi 20480 | Alo 20480 | Bhi 10240 | Blo 10240
#define A_HI_OFF 0
#define A_LO_OFF 20480
#define B_HI_OFF 40960
#define B_LO_OFF 51200
#define STAGE_BYTES 61440
#define NSTAGE 3
#define SMEM_SZ (NSTAGE*STAGE_BYTES)   // 184320
#define ROWB 80                        // padded smem row stride in bytes

typedef __nv_bfloat16 bf16;

// ---------------- static device scratch ----------------
__device__ bf16 g_text_h[(size_t)BROWS*TDIM], g_text_l[(size_t)BROWS*TDIM];
__device__ bf16 g_aud_h [(size_t)BROWS*EDIM], g_aud_l [(size_t)BROWS*EDIM];
__device__ bf16 g_t_h [(size_t)BROWS*EDIM], g_t_l [(size_t)BROWS*EDIM];
__device__ bf16 g_a_h [(size_t)BROWS*EDIM], g_a_l [(size_t)BROWS*EDIM];
__device__ bf16 g_tc_h[(size_t)BROWS*EDIM], g_tc_l[(size_t)BROWS*EDIM];
__device__ bf16 g_ac_h[(size_t)BROWS*EDIM], g_ac_l[(size_t)BROWS*EDIM];
__device__ bf16 g_wt_h [(size_t)EDIM*TDIM],  g_wt_l [(size_t)EDIM*TDIM];
__device__ bf16 g_wa_h [(size_t)EDIM*EDIM],  g_wa_l [(size_t)EDIM*EDIM];
__device__ bf16 g_wo_h [(size_t)EDIM*EDIM],  g_wo_l [(size_t)EDIM*EDIM];
__device__ bf16 g_wvT_h[(size_t)EDIM*EDIM],  g_wvT_l[(size_t)EDIM*EDIM];
__device__ bf16 g_wvo_h[(size_t)EDIM*EDIM],  g_wvo_l[(size_t)EDIM*EDIM];
__device__ bf16 g_wgt_h[(size_t)EDIM*2*EDIM], g_wgt_l[(size_t)EDIM*2*EDIM];
__device__ bf16 g_wga_h[(size_t)EDIM*2*EDIM], g_wga_l[(size_t)EDIM*2*EDIM];
__device__ float g_cv[EDIM];

// ---------------- helpers ----------------
static __device__ __forceinline__ uint32_t s2u(const void* p){
  uint32_t a; asm("{ .reg .u64 t; cvta.to.shared.u64 t, %1; cvt.u32.u64 %0, t; }" : "=r"(a) : "l"(p)); return a;
}

#define LDM4(r, ad) asm volatile( \
  "ldmatrix.sync.aligned.m8n8.x4.shared.b16 {%0,%1,%2,%3}, [%4];" \
  : "=r"((r)[0]),"=r"((r)[1]),"=r"((r)[2]),"=r"((r)[3]) : "r"(ad))

#define MMA(cc, aa, b0, b1) asm volatile( \
  "mma.sync.aligned.m16n8k16.row.col.f32.bf16.bf16.f32 " \
  "{%0,%1,%2,%3},{%4,%5,%6,%7},{%8,%9},{%0,%1,%2,%3};" \
  : "+f"((cc)[0]),"+f"((cc)[1]),"+f"((cc)[2]),"+f"((cc)[3]) \
  : "r"((aa)[0]),"r"((aa)[1]),"r"((aa)[2]),"r"((aa)[3]),"r"(b0),"r"(b1))

#define CP16(dst, src) asm volatile( \
  "cp.async.cg.shared.global [%0], [%1], 16;" :: "r"(dst), "l"(src) : "memory")
#define CP_COMMIT() asm volatile("cp.async.commit_group;" ::: "memory")
#define CP_WAIT(n)  asm volatile("cp.async.wait_group %0;" :: "n"(n) : "memory")

static __device__ __forceinline__ uint32_t pack_bf2(float x, float y){
  __nv_bfloat16 hx=__float2bfloat16(x), hy=__float2bfloat16(y);
  return (uint32_t)__bfloat16_as_ushort(hx) | ((uint32_t)__bfloat16_as_ushort(hy)<<16);
}

// ---------------- pre-conversion kernels ----------------
__global__ void conv_kernel(const float* __restrict__ src, bf16* __restrict__ hi,
                            bf16* __restrict__ lo, int n){
  int i = (blockIdx.x*blockDim.x + threadIdx.x)*4;
  if (i >= n) return;
  float4 v = *(const float4*)(src+i);
  bf16 h0=__float2bfloat16(v.x), h1=__float2bfloat16(v.y);
  bf16 h2=__float2bfloat16(v.z), h3=__float2bfloat16(v.w);
  bf16 l0=__float2bfloat16(v.x-__bfloat162float(h0));
  bf16 l1=__float2bfloat16(v.y-__bfloat162float(h1));
  bf16 l2=__float2bfloat16(v.z-__bfloat162float(h2));
  bf16 l3=__float2bfloat16(v.w-__bfloat162float(h3));
  uint2 ph, pl;
  ph.x=(uint32_t)__bfloat16_as_ushort(h0)|((uint32_t)__bfloat16_as_ushort(h1)<<16);
  ph.y=(uint32_t)__bfloat16_as_ushort(h2)|((uint32_t)__bfloat16_as_ushort(h3)<<16);
  pl.x=(uint32_t)__bfloat16_as_ushort(l0)|((uint32_t)__bfloat16_as_ushort(l1)<<16);
  pl.y=(uint32_t)__bfloat16_as_ushort(l2)|((uint32_t)__bfloat16_as_ushort(l3)<<16);
  *(uint2*)(hi+i)=ph; *(uint2*)(lo+i)=pl;
}

// dst[n][k] = src[k][n], square EDIM x EDIM, split hi/lo
__global__ void convT_kernel(const float* __restrict__ src, bf16* __restrict__ hi,
                             bf16* __restrict__ lo){
  __shared__ float tile[32][33];
  int k0 = blockIdx.y*32, n0 = blockIdx.x*32;
  int tx = threadIdx.x, ty = threadIdx.y;      // 32 x 8
  #pragma unroll
  for (int j=0;j<4;j++)
    tile[ty+j*8][tx] = src[(size_t)(k0+ty+j*8)*EDIM + n0+tx];
  __syncthreads();
  #pragma unroll
  for (int j=0;j<4;j++){
    float v = tile[tx][ty+j*8];
    bf16 h=__float2bfloat16(v);
    bf16 l=__float2bfloat16(v-__bfloat162float(h));
    size_t o = (size_t)(n0+ty+j*8)*EDIM + k0+tx;
    hi[o]=h; lo[o]=l;
  }
}

// cv = Wo @ bv + bo
__global__ void cv_kernel(const float* __restrict__ Wo, const float* __restrict__ bv,
                          const float* __restrict__ bo, float* __restrict__ cv){
  __shared__ float red[128];
  int i = blockIdx.x;
  float s = 0.f;
  for (int k = threadIdx.x; k < EDIM; k += 128) s += Wo[(size_t)i*EDIM + k] * bv[k];
  red[threadIdx.x] = s; __syncthreads();
  for (int off = 64; off; off >>= 1){
    if (threadIdx.x < off) red[threadIdx.x] += red[threadIdx.x+off];
    __syncthreads();
  }
  if (threadIdx.x == 0) cv[i] = red[0] + bo[i];
}

// ---------------- GEMM: C[m][n] = sum_k A[m][k]*B[n][k] + bias ----------------
// A/B given as bf16 hi/lo pairs. A = concat(A1, A2) along k (K1 % 32 == 0).
// GATE=false: write hi/lo bf16 outputs. GATE=true: sigmoid-blend, write fp32 to outf.
// CTA tile 256(M) x 128(N), K-chunk 32, 8 warps as 4x2, warp tile 64x64, 3-stage cp.async.
template<bool GATE>
__global__ void __launch_bounds__(256)
gemm_kernel(const bf16* __restrict__ A1h, const bf16* __restrict__ A1l, int lda1,
            const bf16* __restrict__ A2h, const bf16* __restrict__ A2l, int lda2, int K1,
            const bf16* __restrict__ Bh,  const bf16* __restrict__ Bl,  int ldw,
            const float* __restrict__ bias,
            const bf16* __restrict__ gth, const bf16* __restrict__ gtl,
            const bf16* __restrict__ gch, const bf16* __restrict__ gcl,
            float* __restrict__ outf, bf16* __restrict__ outh, bf16* __restrict__ outl,
            int ldo, int Ktot)
{
  extern __shared__ char smem[];
  const int tid = threadIdx.x, lane = tid & 31, wid = tid >> 5;
  const int mwarp = wid & 3, nwarp = wid >> 2;           // 4 x 2 warp grid
  const int m0 = blockIdx.y * 256, n0 = blockIdx.x * 128;
  const uint32_t sb = s2u(smem);

  float c[4][8][4];
  #pragma unroll
  for (int i=0;i<4;i++)
    #pragma unroll
    for (int j=0;j<8;j++)
      #pragma unroll
      for (int q=0;q<4;q++) c[i][j][q] = 0.f;

  const uint32_t aoff = (uint32_t)((lane&15)*ROWB + ((lane>>4)&1)*16);
  const uint32_t boff = (uint32_t)(((lane&7) + ((lane>>4)&1)*8)*ROWB + ((lane>>3)&1)*16);

  const int nk = Ktot >> 5;

  // issue one K-chunk's cp.asyncs into stage (kc % NSTAGE); one commit group
  #define ISSUE(kc) do { \
    int kk = (kc) << 5; \
    uint32_t st = sb + (uint32_t)((kc)%NSTAGE)*STAGE_BYTES; \
    const bf16 *ah_, *al_; int lda_; \
    if (kk < K1){ ah_ = A1h + (size_t)m0*lda1 + kk; al_ = A1l + (size_t)m0*lda1 + kk; lda_ = lda1; } \
    else        { ah_ = A2h + (size_t)m0*lda2 + (kk-K1); al_ = A2l + (size_t)m0*lda2 + (kk-K1); lda_ = lda2; } \
    _Pragma("unroll") \
    for (int i=0;i<4;i++){ \
      int e = tid + i*256; int row = e>>2, seg = e&3; \
      uint32_t d = st + (uint32_t)(row*ROWB + seg*16); \
      CP16(d,            ah_ + (size_t)row*lda_ + seg*8); \
      CP16(d + A_LO_OFF, al_ + (size_t)row*lda_ + seg*8); \
    } \
    _Pragma("unroll") \
    for (int i=0;i<2;i++){ \
      int e = tid + i*256; int row = e>>2, seg = e&3; \
      uint32_t d = st + B_HI_OFF + (uint32_t)(row*ROWB + seg*16); \
      CP16(d,                         Bh + (size_t)(n0+row)*ldw + kk + seg*8); \
      CP16(d + (B_LO_OFF-B_HI_OFF),   Bl + (size_t)(n0+row)*ldw + kk + seg*8); \
    } \
    CP_COMMIT(); \
  } while(0)

  // prologue: fill all stages
  ISSUE(0); ISSUE(1); ISSUE(2);

  for (int kc = 0; kc < nk; kc++){
    CP_WAIT(2);          // group kc complete (always exactly 3 groups pending)
    __syncthreads();

    // compute chunk kc from stage kc%NSTAGE
    {
      const uint32_t base = sb + (uint32_t)(kc%NSTAGE)*STAGE_BYTES;
      #pragma unroll
      for (int ks=0; ks<2; ks++){
        uint32_t ah[4][4], al[4][4], bb[4][4];
        #pragma unroll
        for (int mi=0;mi<4;mi++){
          uint32_t ad = base + (uint32_t)((mwarp*64 + mi*16)*ROWB + ks*32) + aoff;
          LDM4(ah[mi], ad);
          LDM4(al[mi], ad + (uint32_t)A_LO_OFF);
        }
        #pragma unroll
        for (int bi=0;bi<4;bi++){
          uint32_t bd = base + (uint32_t)B_HI_OFF + (uint32_t)((nwarp*64 + bi*16)*ROWB + ks*32) + boff;
          LDM4(bb[bi], bd);
        }
        // hi*hi
        #pragma unroll
        for (int mi=0;mi<4;mi++)
          #pragma unroll
          for (int ni=0;ni<8;ni++)
            MMA(c[mi][ni], ah[mi], bb[ni>>1][(ni&1)*2], bb[ni>>1][(ni&1)*2+1]);
        // lo*hi
        #pragma unroll
        for (int mi=0;mi<4;mi++)
          #pragma unroll
          for (int ni=0;ni<8;ni++)
            MMA(c[mi][ni], al[mi], bb[ni>>1][(ni&1)*2], bb[ni>>1][(ni&1)*2+1]);
        // B lo (overwrite bb)
        #pragma unroll
        for (int bi=0;bi<4;bi++){
          uint32_t bd = base + (uint32_t)B_LO_OFF + (uint32_t)((nwarp*64 + bi*16)*ROWB + ks*32) + boff;
          LDM4(bb[bi], bd);
        }
        // hi*lo
        #pragma unroll
        for (int mi=0;mi<4;mi++)
          #pragma unroll
          for (int ni=0;ni<8;ni++)
            MMA(c[mi][ni], ah[mi], bb[ni>>1][(ni&1)*2], bb[ni>>1][(ni&1)*2+1]);
      }
    }

    __syncthreads();     // stage kc%NSTAGE free for rewrite
    if (kc+3 < nk) ISSUE(kc+3); else CP_COMMIT();   // keep pending-group count at 3
  }
  #undef ISSUE

  // ---- epilogue ----
  const int gid = lane >> 2, tig = lane & 3;
  #pragma unroll
  for (int mi=0;mi<4;mi++){
    const int rbase = m0 + mwarp*64 + mi*16 + gid;
    #pragma unroll
    for (int ni=0;ni<8;ni++){
      const int col = n0 + nwarp*64 + ni*8 + tig*2;
      const float b0 = bias ? bias[col] : 0.f;
      const float b1 = bias ? bias[col+1] : 0.f;
      #pragma unroll
      for (int half=0; half<2; half++){
        const int r = rbase + half*8;
        float z0 = c[mi][ni][half*2+0] + b0;
        float z1 = c[mi][ni][half*2+1] + b1;
        if (GATE){
          __nv_bfloat162 th = *(const __nv_bfloat162*)(gth + (size_t)r*EDIM + col);
          __nv_bfloat162 tl = *(const __nv_bfloat162*)(gtl + (size_t)r*EDIM + col);
          __nv_bfloat162 ch = *(const __nv_bfloat162*)(gch + (size_t)r*EDIM + col);
          __nv_bfloat162 cl = *(const __nv_bfloat162*)(gcl + (size_t)r*EDIM + col);
          float tv0 = __bfloat162float(th.x)+__bfloat162float(tl.x);
          float tv1 = __bfloat162float(th.y)+__bfloat162float(tl.y);
          float cv0 = __bfloat162float(ch.x)+__bfloat162float(cl.x);
          float cv1 = __bfloat162float(ch.y)+__bfloat162float(cl.y);
          float g0 = 1.f/(1.f + __expf(-z0));
          float g1 = 1.f/(1.f + __expf(-z1));
          float2 o; o.x = g0*tv0 + (1.f-g0)*cv0; o.y = g1*tv1 + (1.f-g1)*cv1;
          *(float2*)(outf + (size_t)r*ldo + col) = o;
        } else {
          bf16 h0=__float2bfloat16(z0), h1=__float2bfloat16(z1);
          float r0 = z0-__bfloat162float(h0), r1 = z1-__bfloat162float(h1);
          uint32_t ph = (uint32_t)__bfloat16_as_ushort(h0)|((uint32_t)__bfloat16_as_ushort(h1)<<16);
          uint32_t pl = pack_bf2(r0, r1);
          *(uint32_t*)(outh + (size_t)r*ldo + col) = ph;
          *(uint32_t*)(outl + (size_t)r*ldo + col) = pl;
        }
      }
    }
  }
}

extern "C" void kernel_launch(void* const* d_in, const int* in_sizes, int n_in,
                              void* d_out, int out_size){
  const float* text = (const float*)d_in[0];
  const float* audio= (const float*)d_in[1];
  const float* Wt = (const float*)d_in[2];  const float* bt = (const float*)d_in[3];
  const float* Wa = (const float*)d_in[4];  const float* ba = (const float*)d_in[5];
  const float* Wv = (const float*)d_in[10]; const float* bv = (const float*)d_in[11];
  const float* Wo = (const float*)d_in[12]; const float* bo = (const float*)d_in[13];
  const float* Wgt= (const float*)d_in[14]; const float* bgt= (const float*)d_in[15];
  const float* Wga= (const float*)d_in[16]; const float* bga= (const float*)d_in[17];
  float* out = (float*)d_out;

  bf16 *texh,*texl,*audh,*audl,*th,*tl,*ah,*al,*tch,*tcl,*ach,*acl;
  bf16 *wth,*wtl,*wah,*wal,*woh,*wol,*wvTh,*wvTl,*wvoh,*wvol,*wgth,*wgtl,*wgah,*wgal;
  float *cv;
  cudaGetSymbolAddress((void**)&texh, g_text_h); cudaGetSymbolAddress((void**)&texl, g_text_l);
  cudaGetSymbolAddress((void**)&audh, g_aud_h);  cudaGetSymbolAddress((void**)&audl, g_aud_l);
  cudaGetSymbolAddress((void**)&th, g_t_h);   cudaGetSymbolAddress((void**)&tl, g_t_l);
  cudaGetSymbolAddress((void**)&ah, g_a_h);   cudaGetSymbolAddress((void**)&al, g_a_l);
  cudaGetSymbolAddress((void**)&tch, g_tc_h); cudaGetSymbolAddress((void**)&tcl, g_tc_l);
  cudaGetSymbolAddress((void**)&ach, g_ac_h); cudaGetSymbolAddress((void**)&acl, g_ac_l);
  cudaGetSymbolAddress((void**)&wth, g_wt_h); cudaGetSymbolAddress((void**)&wtl, g_wt_l);
  cudaGetSymbolAddress((void**)&wah, g_wa_h); cudaGetSymbolAddress((void**)&wal, g_wa_l);
  cudaGetSymbolAddress((void**)&woh, g_wo_h); cudaGetSymbolAddress((void**)&wol, g_wo_l);
  cudaGetSymbolAddress((void**)&wvTh, g_wvT_h); cudaGetSymbolAddress((void**)&wvTl, g_wvT_l);
  cudaGetSymbolAddress((void**)&wvoh, g_wvo_h); cudaGetSymbolAddress((void**)&wvol, g_wvo_l);
  cudaGetSymbolAddress((void**)&wgth, g_wgt_h); cudaGetSymbolAddress((void**)&wgtl, g_wgt_l);
  cudaGetSymbolAddress((void**)&wgah, g_wga_h); cudaGetSymbolAddress((void**)&wgal, g_wga_l);
  cudaGetSymbolAddress((void**)&cv, g_cv);

  cudaFuncSetAttribute(gemm_kernel<false>, cudaFuncAttributeMaxDynamicSharedMemorySize, SMEM_SZ);
  cudaFuncSetAttribute(gemm_kernel<true >, cudaFuncAttributeMaxDynamicSharedMemorySize, SMEM_SZ);

  // ---- conversions (bandwidth-bound, cheap) ----
  auto conv = [](const float* s, bf16* h, bf16* l, size_t n){
    conv_kernel<<<(int)(n/1024), 256>>>(s, h, l, (int)n);
  };
  conv(text, texh, texl, (size_t)BROWS*TDIM);
  conv(audio, audh, audl, (size_t)BROWS*EDIM);
  conv(Wt,  wth, wtl, (size_t)EDIM*TDIM);
  conv(Wa,  wah, wal, (size_t)EDIM*EDIM);
  conv(Wo,  woh, wol, (size_t)EDIM*EDIM);
  conv(Wgt, wgth, wgtl, (size_t)EDIM*2*EDIM);
  conv(Wga, wgah, wgal, (size_t)EDIM*2*EDIM);
  convT_kernel<<<dim3(32,32), dim3(32,8)>>>(Wv, wvTh, wvTl);
  cv_kernel<<<EDIM,128>>>(Wo, bv, bo, cv);

  dim3 gridB(8, BROWS/256);   // 8 x 64 = 512 CTAs

  // Wvo = Wo @ Wv   (A = Wo, B = WvT)
  gemm_kernel<false><<<dim3(8,4), 256, SMEM_SZ>>>(
      woh,wol,EDIM, woh,wol,EDIM, EDIM, wvTh,wvTl,EDIM,
      nullptr, nullptr,nullptr,nullptr,nullptr, nullptr, wvoh, wvol, EDIM, EDIM);
  // t = text @ Wt.T + bt
  gemm_kernel<false><<<gridB, 256, SMEM_SZ>>>(
      texh,texl,TDIM, texh,texl,TDIM, TDIM, wth,wtl,TDIM,
      bt, nullptr,nullptr,nullptr,nullptr, nullptr, th, tl, EDIM, TDIM);
  // a = audio @ Wa.T + ba
  gemm_kernel<false><<<gridB, 256, SMEM_SZ>>>(
      audh,audl,EDIM, audh,audl,EDIM, EDIM, wah,wal,EDIM,
      ba, nullptr,nullptr,nullptr,nullptr, nullptr, ah, al, EDIM, EDIM);
  // t_ctx = a @ Wvo.T + cv
  gemm_kernel<false><<<gridB, 256, SMEM_SZ>>>(
      ah,al,EDIM, ah,al,EDIM, EDIM, wvoh,wvol,EDIM,
      cv, nullptr,nullptr,nullptr,nullptr, nullptr, tch, tcl, EDIM, EDIM);
  // a_ctx = t @ Wvo.T + cv
  gemm_kernel<false><<<gridB, 256, SMEM_SZ>>>(
      th,tl,EDIM, th,tl,EDIM, EDIM, wvoh,wvol,EDIM,
      cv, nullptr,nullptr,nullptr,nullptr, nullptr, ach, acl, EDIM, EDIM);
  // refined_t = gate(concat(t,t_ctx) @ Wgt.T + bgt ; t, t_ctx)
  gemm_kernel<true ><<<gridB, 256, SMEM_SZ>>>(
      th,tl,EDIM, tch,tcl,EDIM, EDIM, wgth,wgtl,2*EDIM,
      bgt, th,tl,tch,tcl, out, nullptr, nullptr, EDIM, 2*EDIM);
  // refined_a = gate(concat(a,a_ctx) @ Wga.T + bga ; a, a_ctx)
  gemm_kernel<true ><<<gridB, 256, SMEM_SZ>>>(
      ah,al,EDIM, ach,acl,EDIM, EDIM, wgah,wgal,2*EDIM,
      bga, ah,al,ach,acl, out + (size_t)BROWS*EDIM, nullptr, nullptr, EDIM, 2*EDIM);
}

// round 12
// speedup vs baseline: 1.3814x; 1.2906x over previous
#include <cuda_runtime.h>
#include <cuda_fp16.h>
#include <cstdint>

#define BROWS 16384
#define EDIM  1024
#define TDIM  768

// GEMM smem stage layout (bytes): Ahi 20480 | Alo 20480 | Bhi 10240
#define A_HI_OFF 0
#define A_LO_OFF 20480
#define B_HI_OFF 40960
#define STAGE_BYTES 51200
#define NSTAGE 3
#define SMEM_SZ (NSTAGE*STAGE_BYTES)   // 153600
#define ROWB 80                        // padded smem row stride in bytes

typedef __half f16;

// ---------------- static device scratch ----------------
__device__ f16 g_text_h[(size_t)BROWS*TDIM], g_text_l[(size_t)BROWS*TDIM];
__device__ f16 g_aud_h [(size_t)BROWS*EDIM], g_aud_l [(size_t)BROWS*EDIM];
__device__ f16 g_t_h [(size_t)BROWS*EDIM], g_t_l [(size_t)BROWS*EDIM];
__device__ f16 g_a_h [(size_t)BROWS*EDIM], g_a_l [(size_t)BROWS*EDIM];
__device__ f16 g_tc_h[(size_t)BROWS*EDIM], g_tc_l[(size_t)BROWS*EDIM];
__device__ f16 g_ac_h[(size_t)BROWS*EDIM], g_ac_l[(size_t)BROWS*EDIM];
__device__ f16 g_wt_h [(size_t)EDIM*TDIM];
__device__ f16 g_wa_h [(size_t)EDIM*EDIM];
__device__ f16 g_wo_h [(size_t)EDIM*EDIM], g_wo_l [(size_t)EDIM*EDIM];
__device__ f16 g_wvT_h[(size_t)EDIM*EDIM];
__device__ f16 g_wvo_h[(size_t)EDIM*EDIM], g_wvo_l[(size_t)EDIM*EDIM];
__device__ f16 g_wgt_h[(size_t)EDIM*2*EDIM];
__device__ f16 g_wga_h[(size_t)EDIM*2*EDIM];
__device__ float g_cv[EDIM];

// ---------------- helpers ----------------
static __device__ __forceinline__ uint32_t s2u(const void* p){
  uint32_t a; asm("{ .reg .u64 t; cvta.to.shared.u64 t, %1; cvt.u32.u64 %0, t; }" : "=r"(a) : "l"(p)); return a;
}

#define LDM4(r, ad) asm volatile( \
  "ldmatrix.sync.aligned.m8n8.x4.shared.b16 {%0,%1,%2,%3}, [%4];" \
  : "=r"((r)[0]),"=r"((r)[1]),"=r"((r)[2]),"=r"((r)[3]) : "r"(ad))

#define MMA(cc, aa, b0, b1) asm volatile( \
  "mma.sync.aligned.m16n8k16.row.col.f32.f16.f16.f32 " \
  "{%0,%1,%2,%3},{%4,%5,%6,%7},{%8,%9},{%0,%1,%2,%3};" \
  : "+f"((cc)[0]),"+f"((cc)[1]),"+f"((cc)[2]),"+f"((cc)[3]) \
  : "r"((aa)[0]),"r"((aa)[1]),"r"((aa)[2]),"r"((aa)[3]),"r"(b0),"r"(b1))

#define CP16(dst, src) asm volatile( \
  "cp.async.cg.shared.global [%0], [%1], 16;" :: "r"(dst), "l"(src) : "memory")
#define CP_COMMIT() asm volatile("cp.async.commit_group;" ::: "memory")
#define CP_WAIT(n)  asm volatile("cp.async.wait_group %0;" :: "n"(n) : "memory")

// ---------------- pre-conversion kernels ----------------
// fp32 -> fp16 hi/lo pair (A-side tensors)
__global__ void conv_hl_kernel(const float* __restrict__ src, f16* __restrict__ hi,
                               f16* __restrict__ lo, int n){
  int i = (blockIdx.x*blockDim.x + threadIdx.x)*4;
  if (i >= n) return;
  float4 v = *(const float4*)(src+i);
  f16 h0=__float2half_rn(v.x), h1=__float2half_rn(v.y);
  f16 h2=__float2half_rn(v.z), h3=__float2half_rn(v.w);
  f16 l0=__float2half_rn(v.x-__half2float(h0));
  f16 l1=__float2half_rn(v.y-__half2float(h1));
  f16 l2=__float2half_rn(v.z-__half2float(h2));
  f16 l3=__float2half_rn(v.w-__half2float(h3));
  uint2 ph, pl;
  ph.x=(uint32_t)__half_as_ushort(h0)|((uint32_t)__half_as_ushort(h1)<<16);
  ph.y=(uint32_t)__half_as_ushort(h2)|((uint32_t)__half_as_ushort(h3)<<16);
  pl.x=(uint32_t)__half_as_ushort(l0)|((uint32_t)__half_as_ushort(l1)<<16);
  pl.y=(uint32_t)__half_as_ushort(l2)|((uint32_t)__half_as_ushort(l3)<<16);
  *(uint2*)(hi+i)=ph; *(uint2*)(lo+i)=pl;
}
// fp32 -> fp16 hi only (B-side weights)
__global__ void conv_h_kernel(const float* __restrict__ src, f16* __restrict__ hi, int n){
  int i = (blockIdx.x*blockDim.x + threadIdx.x)*4;
  if (i >= n) return;
  float4 v = *(const float4*)(src+i);
  uint2 ph;
  ph.x=(uint32_t)__half_as_ushort(__float2half_rn(v.x))|((uint32_t)__half_as_ushort(__float2half_rn(v.y))<<16);
  ph.y=(uint32_t)__half_as_ushort(__float2half_rn(v.z))|((uint32_t)__half_as_ushort(__float2half_rn(v.w))<<16);
  *(uint2*)(hi+i)=ph;
}
// dst[n][k] = src[k][n], EDIM x EDIM, hi only
__global__ void convT_kernel(const float* __restrict__ src, f16* __restrict__ hi){
  __shared__ float tile[32][33];
  int k0 = blockIdx.y*32, n0 = blockIdx.x*32;
  int tx = threadIdx.x, ty = threadIdx.y;      // 32 x 8
  #pragma unroll
  for (int j=0;j<4;j++)
    tile[ty+j*8][tx] = src[(size_t)(k0+ty+j*8)*EDIM + n0+tx];
  __syncthreads();
  #pragma unroll
  for (int j=0;j<4;j++){
    float v = tile[tx][ty+j*8];
    hi[(size_t)(n0+ty+j*8)*EDIM + k0+tx] = __float2half_rn(v);
  }
}
// cv = Wo @ bv + bo
__global__ void cv_kernel(const float* __restrict__ Wo, const float* __restrict__ bv,
                          const float* __restrict__ bo, float* __restrict__ cv){
  __shared__ float red[128];
  int i = blockIdx.x;
  float s = 0.f;
  for (int k = threadIdx.x; k < EDIM; k += 128) s += Wo[(size_t)i*EDIM + k] * bv[k];
  red[threadIdx.x] = s; __syncthreads();
  for (int off = 64; off; off >>= 1){
    if (threadIdx.x < off) red[threadIdx.x] += red[threadIdx.x+off];
    __syncthreads();
  }
  if (threadIdx.x == 0) cv[i] = red[0] + bo[i];
}

// ---------------- GEMM: C[m][n] = sum_k A[m][k]*B[n][k] + bias ----------------
// fp16x2: C = Ah*Bh + Al*Bh (B lo dropped; ~1.5e-4 rel). A = concat(A1,A2), K1%32==0.
// GATE=false: write fp16 hi/lo outputs. GATE=true: sigmoid-blend, write fp32.
// CTA tile 256x128, K-chunk 32, 8 warps 4x2, warp tile 64x64, 3-stage cp.async.
template<bool GATE>
__global__ void __launch_bounds__(256)
gemm_kernel(const f16* __restrict__ A1h, const f16* __restrict__ A1l, int lda1,
            const f16* __restrict__ A2h, const f16* __restrict__ A2l, int lda2, int K1,
            const f16* __restrict__ Bh, int ldw,
            const float* __restrict__ bias,
            const f16* __restrict__ gth, const f16* __restrict__ gtl,
            const f16* __restrict__ gch, const f16* __restrict__ gcl,
            float* __restrict__ outf, f16* __restrict__ outh, f16* __restrict__ outl,
            int ldo, int Ktot)
{
  extern __shared__ char smem[];
  const int tid = threadIdx.x, lane = tid & 31, wid = tid >> 5;
  const int mwarp = wid & 3, nwarp = wid >> 2;           // 4 x 2 warp grid
  const int m0 = blockIdx.y * 256, n0 = blockIdx.x * 128;
  const uint32_t sb = s2u(smem);

  float c[4][8][4];
  #pragma unroll
  for (int i=0;i<4;i++)
    #pragma unroll
    for (int j=0;j<8;j++)
      #pragma unroll
      for (int q=0;q<4;q++) c[i][j][q] = 0.f;

  const uint32_t aoff = (uint32_t)((lane&15)*ROWB + ((lane>>4)&1)*16);
  const uint32_t boff = (uint32_t)(((lane&7) + ((lane>>4)&1)*8)*ROWB + ((lane>>3)&1)*16);

  const int nk = Ktot >> 5;

  #define ISSUE(kc) do { \
    int kk = (kc) << 5; \
    uint32_t st = sb + (uint32_t)((kc)%NSTAGE)*STAGE_BYTES; \
    const f16 *ah_, *al_; int lda_; \
    if (kk < K1){ ah_ = A1h + (size_t)m0*lda1 + kk; al_ = A1l + (size_t)m0*lda1 + kk; lda_ = lda1; } \
    else        { ah_ = A2h + (size_t)m0*lda2 + (kk-K1); al_ = A2l + (size_t)m0*lda2 + (kk-K1); lda_ = lda2; } \
    _Pragma("unroll") \
    for (int i=0;i<4;i++){ \
      int e = tid + i*256; int row = e>>2, seg = e&3; \
      uint32_t d = st + (uint32_t)(row*ROWB + seg*16); \
      CP16(d,            ah_ + (size_t)row*lda_ + seg*8); \
      CP16(d + A_LO_OFF, al_ + (size_t)row*lda_ + seg*8); \
    } \
    _Pragma("unroll") \
    for (int i=0;i<2;i++){ \
      int e = tid + i*256; int row = e>>2, seg = e&3; \
      uint32_t d = st + B_HI_OFF + (uint32_t)(row*ROWB + seg*16); \
      CP16(d, Bh + (size_t)(n0+row)*ldw + kk + seg*8); \
    } \
    CP_COMMIT(); \
  } while(0)

  ISSUE(0); ISSUE(1); ISSUE(2);

  for (int kc = 0; kc < nk; kc++){
    CP_WAIT(2);
    __syncthreads();
    {
      const uint32_t base = sb + (uint32_t)(kc%NSTAGE)*STAGE_BYTES;
      #pragma unroll
      for (int ks=0; ks<2; ks++){
        uint32_t ah[4][4], al[4][4], bb[4][4];
        #pragma unroll
        for (int mi=0;mi<4;mi++){
          uint32_t ad = base + (uint32_t)((mwarp*64 + mi*16)*ROWB + ks*32) + aoff;
          LDM4(ah[mi], ad);
          LDM4(al[mi], ad + (uint32_t)A_LO_OFF);
        }
        #pragma unroll
        for (int bi=0;bi<4;bi++){
          uint32_t bd = base + (uint32_t)B_HI_OFF + (uint32_t)((nwarp*64 + bi*16)*ROWB + ks*32) + boff;
          LDM4(bb[bi], bd);
        }
        // hi*hi
        #pragma unroll
        for (int mi=0;mi<4;mi++)
          #pragma unroll
          for (int ni=0;ni<8;ni++)
            MMA(c[mi][ni], ah[mi], bb[ni>>1][(ni&1)*2], bb[ni>>1][(ni&1)*2+1]);
        // lo*hi (B fragments reused from registers)
        #pragma unroll
        for (int mi=0;mi<4;mi++)
          #pragma unroll
          for (int ni=0;ni<8;ni++)
            MMA(c[mi][ni], al[mi], bb[ni>>1][(ni&1)*2], bb[ni>>1][(ni&1)*2+1]);
      }
    }
    __syncthreads();
    if (kc+3 < nk) ISSUE(kc+3); else CP_COMMIT();
  }
  #undef ISSUE

  // ---- epilogue ----
  const int gid = lane >> 2, tig = lane & 3;
  #pragma unroll
  for (int mi=0;mi<4;mi++){
    const int rbase = m0 + mwarp*64 + mi*16 + gid;
    #pragma unroll
    for (int ni=0;ni<8;ni++){
      const int col = n0 + nwarp*64 + ni*8 + tig*2;
      const float b0 = bias ? bias[col] : 0.f;
      const float b1 = bias ? bias[col+1] : 0.f;
      #pragma unroll
      for (int half_=0; half_<2; half_++){
        const int r = rbase + half_*8;
        float z0 = c[mi][ni][half_*2+0] + b0;
        float z1 = c[mi][ni][half_*2+1] + b1;
        if (GATE){
          __half2 th = *(const __half2*)(gth + (size_t)r*EDIM + col);
          __half2 tl = *(const __half2*)(gtl + (size_t)r*EDIM + col);
          __half2 ch = *(const __half2*)(gch + (size_t)r*EDIM + col);
          __half2 cl = *(const __half2*)(gcl + (size_t)r*EDIM + col);
          float tv0 = __half2float(th.x)+__half2float(tl.x);
          float tv1 = __half2float(th.y)+__half2float(tl.y);
          float cv0 = __half2float(ch.x)+__half2float(cl.x);
          float cv1 = __half2float(ch.y)+__half2float(cl.y);
          float g0 = 1.f/(1.f + __expf(-z0));
          float g1 = 1.f/(1.f + __expf(-z1));
          float2 o; o.x = g0*tv0 + (1.f-g0)*cv0; o.y = g1*tv1 + (1.f-g1)*cv1;
          *(float2*)(outf + (size_t)r*ldo + col) = o;
        } else {
          f16 h0=__float2half_rn(z0), h1=__float2half_rn(z1);
          f16 l0=__float2half_rn(z0-__half2float(h0));
          f16 l1=__float2half_rn(z1-__half2float(h1));
          uint32_t ph = (uint32_t)__half_as_ushort(h0)|((uint32_t)__half_as_ushort(h1)<<16);
          uint32_t pl = (uint32_t)__half_as_ushort(l0)|((uint32_t)__half_as_ushort(l1)<<16);
          *(uint32_t*)(outh + (size_t)r*ldo + col) = ph;
          *(uint32_t*)(outl + (size_t)r*ldo + col) = pl;
        }
      }
    }
  }
}

extern "C" void kernel_launch(void* const* d_in, const int* in_sizes, int n_in,
                              void* d_out, int out_size){
  const float* text = (const float*)d_in[0];
  const float* audio= (const float*)d_in[1];
  const float* Wt = (const float*)d_in[2];  const float* bt = (const float*)d_in[3];
  const float* Wa = (const float*)d_in[4];  const float* ba = (const float*)d_in[5];
  const float* Wv = (const float*)d_in[10]; const float* bv = (const float*)d_in[11];
  const float* Wo = (const float*)d_in[12]; const float* bo = (const float*)d_in[13];
  const float* Wgt= (const float*)d_in[14]; const float* bgt= (const float*)d_in[15];
  const float* Wga= (const float*)d_in[16]; const float* bga= (const float*)d_in[17];
  float* out = (float*)d_out;

  f16 *texh,*texl,*audh,*audl,*th,*tl,*ah,*al,*tch,*tcl,*ach,*acl;
  f16 *wth,*wah,*woh,*wol,*wvTh,*wvoh,*wvol,*wgth,*wgah;
  float *cv;
  cudaGetSymbolAddress((void**)&texh, g_text_h); cudaGetSymbolAddress((void**)&texl, g_text_l);
  cudaGetSymbolAddress((void**)&audh, g_aud_h);  cudaGetSymbolAddress((void**)&audl, g_aud_l);
  cudaGetSymbolAddress((void**)&th, g_t_h);   cudaGetSymbolAddress((void**)&tl, g_t_l);
  cudaGetSymbolAddress((void**)&ah, g_a_h);   cudaGetSymbolAddress((void**)&al, g_a_l);
  cudaGetSymbolAddress((void**)&tch, g_tc_h); cudaGetSymbolAddress((void**)&tcl, g_tc_l);
  cudaGetSymbolAddress((void**)&ach, g_ac_h); cudaGetSymbolAddress((void**)&acl, g_ac_l);
  cudaGetSymbolAddress((void**)&wth, g_wt_h);
  cudaGetSymbolAddress((void**)&wah, g_wa_h);
  cudaGetSymbolAddress((void**)&woh, g_wo_h); cudaGetSymbolAddress((void**)&wol, g_wo_l);
  cudaGetSymbolAddress((void**)&wvTh, g_wvT_h);
  cudaGetSymbolAddress((void**)&wvoh, g_wvo_h); cudaGetSymbolAddress((void**)&wvol, g_wvo_l);
  cudaGetSymbolAddress((void**)&wgth, g_wgt_h);
  cudaGetSymbolAddress((void**)&wgah, g_wga_h);
  cudaGetSymbolAddress((void**)&cv, g_cv);

  cudaFuncSetAttribute(gemm_kernel<false>, cudaFuncAttributeMaxDynamicSharedMemorySize, SMEM_SZ);
  cudaFuncSetAttribute(gemm_kernel<true >, cudaFuncAttributeMaxDynamicSharedMemorySize, SMEM_SZ);

  // ---- conversions ----
  conv_hl_kernel<<<(BROWS*TDIM)/1024, 256>>>(text, texh, texl, BROWS*TDIM);
  conv_hl_kernel<<<(BROWS*EDIM)/1024, 256>>>(audio, audh, audl, BROWS*EDIM);
  conv_hl_kernel<<<(EDIM*EDIM)/1024, 256>>>(Wo, woh, wol, EDIM*EDIM);
  conv_h_kernel<<<(EDIM*TDIM)/1024, 256>>>(Wt, wth, EDIM*TDIM);
  conv_h_kernel<<<(EDIM*EDIM)/1024, 256>>>(Wa, wah, EDIM*EDIM);
  conv_h_kernel<<<(EDIM*2*EDIM)/1024, 256>>>(Wgt, wgth, EDIM*2*EDIM);
  conv_h_kernel<<<(EDIM*2*EDIM)/1024, 256>>>(Wga, wgah, EDIM*2*EDIM);
  convT_kernel<<<dim3(32,32), dim3(32,8)>>>(Wv, wvTh);
  cv_kernel<<<EDIM,128>>>(Wo, bv, bo, cv);

  dim3 gridB(8, BROWS/256);   // 8 x 64 = 512 CTAs

  // Wvo = Wo @ Wv   (A = Wo hi/lo, B = WvT hi)
  gemm_kernel<false><<<dim3(8,4), 256, SMEM_SZ>>>(
      woh,wol,EDIM, woh,wol,EDIM, EDIM, wvTh,EDIM,
      nullptr, nullptr,nullptr,nullptr,nullptr, nullptr, wvoh, wvol, EDIM, EDIM);
  // t = text @ Wt.T + bt
  gemm_kernel<false><<<gridB, 256, SMEM_SZ>>>(
      texh,texl,TDIM, texh,texl,TDIM, TDIM, wth,TDIM,
      bt, nullptr,nullptr,nullptr,nullptr, nullptr, th, tl, EDIM, TDIM);
  // a = audio @ Wa.T + ba
  gemm_kernel<false><<<gridB, 256, SMEM_SZ>>>(
      audh,audl,EDIM, audh,audl,EDIM, EDIM, wah,EDIM,
      ba, nullptr,nullptr,nullptr,nullptr, nullptr, ah, al, EDIM, EDIM);
  // t_ctx = a @ Wvo.T + cv
  gemm_kernel<false><<<gridB, 256, SMEM_SZ>>>(
      ah,al,EDIM, ah,al,EDIM, EDIM, wvoh,EDIM,
      cv, nullptr,nullptr,nullptr,nullptr, nullptr, tch, tcl, EDIM, EDIM);
  // a_ctx = t @ Wvo.T + cv
  gemm_kernel<false><<<gridB, 256, SMEM_SZ>>>(
      th,tl,EDIM, th,tl,EDIM, EDIM, wvoh,EDIM,
      cv, nullptr,nullptr,nullptr,nullptr, nullptr, ach, acl, EDIM, EDIM);
  // refined_t = gate(concat(t,t_ctx) @ Wgt.T + bgt ; t, t_ctx)
  gemm_kernel<true ><<<gridB, 256, SMEM_SZ>>>(
      th,tl,EDIM, tch,tcl,EDIM, EDIM, wgth,2*EDIM,
      bgt, th,tl,tch,tcl, out, nullptr, nullptr, EDIM, 2*EDIM);
  // refined_a = gate(concat(a,a_ctx) @ Wga.T + bga ; a, a_ctx)
  gemm_kernel<true ><<<gridB, 256, SMEM_SZ>>>(
      ah,al,EDIM, ach,acl,EDIM, EDIM, wgah,2*EDIM,
      bga, ah,al,ach,acl, out + (size_t)BROWS*EDIM, nullptr, nullptr, EDIM, 2*EDIM);
}

// round 14
// speedup vs baseline: 1.8492x; 1.3387x over previous
#include <cuda_runtime.h>
#include <cuda_fp16.h>
#include <cstdint>

#define BROWS 16384
#define EDIM  1024
#define TDIM  768
#define NSTAGE 3
#define ROWB 80                        // padded smem row stride in bytes

typedef __half f16;

// ---------------- static device scratch ----------------
__device__ f16 g_text_h[(size_t)BROWS*TDIM], g_text_l[(size_t)BROWS*TDIM];
__device__ f16 g_aud_h [(size_t)BROWS*EDIM], g_aud_l [(size_t)BROWS*EDIM];
__device__ f16 g_t_h [(size_t)BROWS*EDIM], g_t_l [(size_t)BROWS*EDIM];
__device__ f16 g_a_h [(size_t)BROWS*EDIM], g_a_l [(size_t)BROWS*EDIM];
__device__ f16 g_tc_h[(size_t)BROWS*EDIM], g_tc_l[(size_t)BROWS*EDIM];
__device__ f16 g_ac_h[(size_t)BROWS*EDIM], g_ac_l[(size_t)BROWS*EDIM];
__device__ f16 g_wt_h [(size_t)EDIM*TDIM];
__device__ f16 g_wa_h [(size_t)EDIM*EDIM];
__device__ f16 g_wo_h [(size_t)EDIM*EDIM], g_wo_l [(size_t)EDIM*EDIM];
__device__ f16 g_wvT_h[(size_t)EDIM*EDIM];
__device__ f16 g_wvo_h[(size_t)EDIM*EDIM], g_wvo_l[(size_t)EDIM*EDIM];
__device__ f16 g_wgt_h[(size_t)EDIM*2*EDIM];
__device__ f16 g_wga_h[(size_t)EDIM*2*EDIM];
__device__ float g_cv[EDIM];

// ---------------- helpers ----------------
static __device__ __forceinline__ uint32_t s2u(const void* p){
  uint32_t a; asm("{ .reg .u64 t; cvta.to.shared.u64 t, %1; cvt.u32.u64 %0, t; }" : "=r"(a) : "l"(p)); return a;
}

#define LDM4(r, ad) asm volatile( \
  "ldmatrix.sync.aligned.m8n8.x4.shared.b16 {%0,%1,%2,%3}, [%4];" \
  : "=r"((r)[0]),"=r"((r)[1]),"=r"((r)[2]),"=r"((r)[3]) : "r"(ad))

#define MMA(cc, aa, b0, b1) asm volatile( \
  "mma.sync.aligned.m16n8k16.row.col.f32.f16.f16.f32 " \
  "{%0,%1,%2,%3},{%4,%5,%6,%7},{%8,%9},{%0,%1,%2,%3};" \
  : "+f"((cc)[0]),"+f"((cc)[1]),"+f"((cc)[2]),"+f"((cc)[3]) \
  : "r"((aa)[0]),"r"((aa)[1]),"r"((aa)[2]),"r"((aa)[3]),"r"(b0),"r"(b1))

#define CP16(dst, src) asm volatile( \
  "cp.async.cg.shared.global [%0], [%1], 16;" :: "r"(dst), "l"(src) : "memory")
#define CP_COMMIT() asm volatile("cp.async.commit_group;" ::: "memory")
#define CP_WAIT(n)  asm volatile("cp.async.wait_group %0;" :: "n"(n) : "memory")

// ---------------- pre-conversion kernels ----------------
__global__ void conv_hl_kernel(const float* __restrict__ src, f16* __restrict__ hi,
                               f16* __restrict__ lo, int n){
  int i = (blockIdx.x*blockDim.x + threadIdx.x)*4;
  if (i >= n) return;
  float4 v = *(const float4*)(src+i);
  f16 h0=__float2half_rn(v.x), h1=__float2half_rn(v.y);
  f16 h2=__float2half_rn(v.z), h3=__float2half_rn(v.w);
  f16 l0=__float2half_rn(v.x-__half2float(h0));
  f16 l1=__float2half_rn(v.y-__half2float(h1));
  f16 l2=__float2half_rn(v.z-__half2float(h2));
  f16 l3=__float2half_rn(v.w-__half2float(h3));
  uint2 ph, pl;
  ph.x=(uint32_t)__half_as_ushort(h0)|((uint32_t)__half_as_ushort(h1)<<16);
  ph.y=(uint32_t)__half_as_ushort(h2)|((uint32_t)__half_as_ushort(h3)<<16);
  pl.x=(uint32_t)__half_as_ushort(l0)|((uint32_t)__half_as_ushort(l1)<<16);
  pl.y=(uint32_t)__half_as_ushort(l2)|((uint32_t)__half_as_ushort(l3)<<16);
  *(uint2*)(hi+i)=ph; *(uint2*)(lo+i)=pl;
}
__global__ void conv_h_kernel(const float* __restrict__ src, f16* __restrict__ hi, int n){
  int i = (blockIdx.x*blockDim.x + threadIdx.x)*4;
  if (i >= n) return;
  float4 v = *(const float4*)(src+i);
  uint2 ph;
  ph.x=(uint32_t)__half_as_ushort(__float2half_rn(v.x))|((uint32_t)__half_as_ushort(__float2half_rn(v.y))<<16);
  ph.y=(uint32_t)__half_as_ushort(__float2half_rn(v.z))|((uint32_t)__half_as_ushort(__float2half_rn(v.w))<<16);
  *(uint2*)(hi+i)=ph;
}
__global__ void convT_kernel(const float* __restrict__ src, f16* __restrict__ hi){
  __shared__ float tile[32][33];
  int k0 = blockIdx.y*32, n0 = blockIdx.x*32;
  int tx = threadIdx.x, ty = threadIdx.y;      // 32 x 8
  #pragma unroll
  for (int j=0;j<4;j++)
    tile[ty+j*8][tx] = src[(size_t)(k0+ty+j*8)*EDIM + n0+tx];
  __syncthreads();
  #pragma unroll
  for (int j=0;j<4;j++){
    float v = tile[tx][ty+j*8];
    hi[(size_t)(n0+ty+j*8)*EDIM + k0+tx] = __float2half_rn(v);
  }
}
__global__ void cv_kernel(const float* __restrict__ Wo, const float* __restrict__ bv,
                          const float* __restrict__ bo, float* __restrict__ cv){
  __shared__ float red[128];
  int i = blockIdx.x;
  float s = 0.f;
  for (int k = threadIdx.x; k < EDIM; k += 128) s += Wo[(size_t)i*EDIM + k] * bv[k];
  red[threadIdx.x] = s; __syncthreads();
  for (int off = 64; off; off >>= 1){
    if (threadIdx.x < off) red[threadIdx.x] += red[threadIdx.x+off];
    __syncthreads();
  }
  if (threadIdx.x == 0) cv[i] = red[0] + bo[i];
}

// ---------------- GEMM params ----------------
struct GP {
  const f16 *A1h, *A1l; int lda1;
  const f16 *A2h, *A2l; int lda2; int K1;
  const f16 *Bh; int ldw;
  const float* bias;
  const f16 *gth, *gtl, *gch, *gcl;
  float* outf; f16 *outh, *outl;
  int ldo; int Ktot;
};

// C[m][n] = sum_k A[m][k]*B[n][k] + bias.
// TWOPASS: C = Ah*Bh + Al*Bh. else single pass Ah*Bh.
// GATE: sigmoid-blend epilogue -> fp32 out; else fp16 hi/lo outputs.
// CTA tile 256x128, K-chunk 32, 8 warps 4x2, warp tile 64x64, 3-stage cp.async.
// blockIdx.z selects p0/p1 (merged launches).
template<bool GATE, bool TWOPASS>
__global__ void __launch_bounds__(256)
gemm_kernel(GP p0, GP p1)
{
  constexpr uint32_t ALO = 20480;
  constexpr uint32_t BOF = TWOPASS ? 40960u : 20480u;
  constexpr uint32_t STB = TWOPASS ? 51200u : 30720u;

  const GP p = blockIdx.z ? p1 : p0;
  extern __shared__ char smem[];
  const int tid = threadIdx.x, lane = tid & 31, wid = tid >> 5;
  const int mwarp = wid & 3, nwarp = wid >> 2;           // 4 x 2 warp grid
  const int m0 = blockIdx.y * 256, n0 = blockIdx.x * 128;
  const uint32_t sb = s2u(smem);

  float c[4][8][4];
  #pragma unroll
  for (int i=0;i<4;i++)
    #pragma unroll
    for (int j=0;j<8;j++)
      #pragma unroll
      for (int q=0;q<4;q++) c[i][j][q] = 0.f;

  const uint32_t aoff = (uint32_t)((lane&15)*ROWB + ((lane>>4)&1)*16);
  const uint32_t boff = (uint32_t)(((lane&7) + ((lane>>4)&1)*8)*ROWB + ((lane>>3)&1)*16);

  const int nk = p.Ktot >> 5;

  #define ISSUE(kc) do { \
    int kk = (kc) << 5; \
    uint32_t st = sb + (uint32_t)((kc)%NSTAGE)*STB; \
    const f16 *ah_, *al_; int lda_; \
    if (kk < p.K1){ ah_ = p.A1h + (size_t)m0*p.lda1 + kk; al_ = p.A1l + (size_t)m0*p.lda1 + kk; lda_ = p.lda1; } \
    else          { ah_ = p.A2h + (size_t)m0*p.lda2 + (kk-p.K1); al_ = p.A2l + (size_t)m0*p.lda2 + (kk-p.K1); lda_ = p.lda2; } \
    _Pragma("unroll") \
    for (int i=0;i<4;i++){ \
      int e = tid + i*256; int row = e>>2, seg = e&3; \
      uint32_t d = st + (uint32_t)(row*ROWB + seg*16); \
      CP16(d, ah_ + (size_t)row*lda_ + seg*8); \
      if (TWOPASS) CP16(d + ALO, al_ + (size_t)row*lda_ + seg*8); \
    } \
    _Pragma("unroll") \
    for (int i=0;i<2;i++){ \
      int e = tid + i*256; int row = e>>2, seg = e&3; \
      uint32_t d = st + BOF + (uint32_t)(row*ROWB + seg*16); \
      CP16(d, p.Bh + (size_t)(n0+row)*p.ldw + kk + seg*8); \
    } \
    CP_COMMIT(); \
  } while(0)

  ISSUE(0); ISSUE(1); ISSUE(2);

  for (int kc = 0; kc < nk; kc++){
    CP_WAIT(2);
    __syncthreads();
    {
      const uint32_t base = sb + (uint32_t)(kc%NSTAGE)*STB;
      #pragma unroll
      for (int ks=0; ks<2; ks++){
        uint32_t ah[4][4], al[4][4], bb[4][4];
        #pragma unroll
        for (int mi=0;mi<4;mi++){
          uint32_t ad = base + (uint32_t)((mwarp*64 + mi*16)*ROWB + ks*32) + aoff;
          LDM4(ah[mi], ad);
          if (TWOPASS) LDM4(al[mi], ad + ALO);
        }
        #pragma unroll
        for (int bi=0;bi<4;bi++){
          uint32_t bd = base + BOF + (uint32_t)((nwarp*64 + bi*16)*ROWB + ks*32) + boff;
          LDM4(bb[bi], bd);
        }
        #pragma unroll
        for (int mi=0;mi<4;mi++)
          #pragma unroll
          for (int ni=0;ni<8;ni++)
            MMA(c[mi][ni], ah[mi], bb[ni>>1][(ni&1)*2], bb[ni>>1][(ni&1)*2+1]);
        if (TWOPASS){
          #pragma unroll
          for (int mi=0;mi<4;mi++)
            #pragma unroll
            for (int ni=0;ni<8;ni++)
              MMA(c[mi][ni], al[mi], bb[ni>>1][(ni&1)*2], bb[ni>>1][(ni&1)*2+1]);
        }
      }
    }
    __syncthreads();
    if (kc+3 < nk) ISSUE(kc+3); else CP_COMMIT();
  }
  #undef ISSUE

  // ---- epilogue ----
  const int gid = lane >> 2, tig = lane & 3;
  #pragma unroll
  for (int mi=0;mi<4;mi++){
    const int rbase = m0 + mwarp*64 + mi*16 + gid;
    #pragma unroll
    for (int ni=0;ni<8;ni++){
      const int col = n0 + nwarp*64 + ni*8 + tig*2;
      const float b0 = p.bias ? p.bias[col] : 0.f;
      const float b1 = p.bias ? p.bias[col+1] : 0.f;
      #pragma unroll
      for (int half_=0; half_<2; half_++){
        const int r = rbase + half_*8;
        float z0 = c[mi][ni][half_*2+0] + b0;
        float z1 = c[mi][ni][half_*2+1] + b1;
        if (GATE){
          __half2 th = *(const __half2*)(p.gth + (size_t)r*EDIM + col);
          __half2 tl = *(const __half2*)(p.gtl + (size_t)r*EDIM + col);
          __half2 ch = *(const __half2*)(p.gch + (size_t)r*EDIM + col);
          __half2 cl = *(const __half2*)(p.gcl + (size_t)r*EDIM + col);
          float tv0 = __half2float(th.x)+__half2float(tl.x);
          float tv1 = __half2float(th.y)+__half2float(tl.y);
          float cv0 = __half2float(ch.x)+__half2float(cl.x);
          float cv1 = __half2float(ch.y)+__half2float(cl.y);
          float g0 = 1.f/(1.f + __expf(-z0));
          float g1 = 1.f/(1.f + __expf(-z1));
          float2 o; o.x = g0*tv0 + (1.f-g0)*cv0; o.y = g1*tv1 + (1.f-g1)*cv1;
          *(float2*)(p.outf + (size_t)r*p.ldo + col) = o;
        } else {
          f16 h0=__float2half_rn(z0), h1=__float2half_rn(z1);
          f16 l0=__float2half_rn(z0-__half2float(h0));
          f16 l1=__float2half_rn(z1-__half2float(h1));
          uint32_t ph = (uint32_t)__half_as_ushort(h0)|((uint32_t)__half_as_ushort(h1)<<16);
          uint32_t pl = (uint32_t)__half_as_ushort(l0)|((uint32_t)__half_as_ushort(l1)<<16);
          *(uint32_t*)(p.outh + (size_t)r*p.ldo + col) = ph;
          *(uint32_t*)(p.outl + (size_t)r*p.ldo + col) = pl;
        }
      }
    }
  }
}

extern "C" void kernel_launch(void* const* d_in, const int* in_sizes, int n_in,
                              void* d_out, int out_size){
  const float* text = (const float*)d_in[0];
  const float* audio= (const float*)d_in[1];
  const float* Wt = (const float*)d_in[2];  const float* bt = (const float*)d_in[3];
  const float* Wa = (const float*)d_in[4];  const float* ba = (const float*)d_in[5];
  const float* Wv = (const float*)d_in[10]; const float* bv = (const float*)d_in[11];
  const float* Wo = (const float*)d_in[12]; const float* bo = (const float*)d_in[13];
  const float* Wgt= (const float*)d_in[14]; const float* bgt= (const float*)d_in[15];
  const float* Wga= (const float*)d_in[16]; const float* bga= (const float*)d_in[17];
  float* out = (float*)d_out;

  f16 *texh,*texl,*audh,*audl,*th,*tl,*ah,*al,*tch,*tcl,*ach,*acl;
  f16 *wth,*wah,*woh,*wol,*wvTh,*wvoh,*wvol,*wgth,*wgah;
  float *cv;
  cudaGetSymbolAddress((void**)&texh, g_text_h); cudaGetSymbolAddress((void**)&texl, g_text_l);
  cudaGetSymbolAddress((void**)&audh, g_aud_h);  cudaGetSymbolAddress((void**)&audl, g_aud_l);
  cudaGetSymbolAddress((void**)&th, g_t_h);   cudaGetSymbolAddress((void**)&tl, g_t_l);
  cudaGetSymbolAddress((void**)&ah, g_a_h);   cudaGetSymbolAddress((void**)&al, g_a_l);
  cudaGetSymbolAddress((void**)&tch, g_tc_h); cudaGetSymbolAddress((void**)&tcl, g_tc_l);
  cudaGetSymbolAddress((void**)&ach, g_ac_h); cudaGetSymbolAddress((void**)&acl, g_ac_l);
  cudaGetSymbolAddress((void**)&wth, g_wt_h);
  cudaGetSymbolAddress((void**)&wah, g_wa_h);
  cudaGetSymbolAddress((void**)&woh, g_wo_h); cudaGetSymbolAddress((void**)&wol, g_wo_l);
  cudaGetSymbolAddress((void**)&wvTh, g_wvT_h);
  cudaGetSymbolAddress((void**)&wvoh, g_wvo_h); cudaGetSymbolAddress((void**)&wvol, g_wvo_l);
  cudaGetSymbolAddress((void**)&wgth, g_wgt_h);
  cudaGetSymbolAddress((void**)&wgah, g_wga_h);
  cudaGetSymbolAddress((void**)&cv, g_cv);

  const int SM2 = 3*51200;   // two-pass stage bytes
  const int SM1 = 3*30720;   // single-pass
  cudaFuncSetAttribute(gemm_kernel<false,true >, cudaFuncAttributeMaxDynamicSharedMemorySize, SM2);
  cudaFuncSetAttribute(gemm_kernel<true ,false>, cudaFuncAttributeMaxDynamicSharedMemorySize, SM1);

  // ---- conversions ----
  conv_hl_kernel<<<(BROWS*TDIM)/1024, 256>>>(text, texh, texl, BROWS*TDIM);
  conv_hl_kernel<<<(BROWS*EDIM)/1024, 256>>>(audio, audh, audl, BROWS*EDIM);
  conv_hl_kernel<<<(EDIM*EDIM)/1024, 256>>>(Wo, woh, wol, EDIM*EDIM);
  conv_h_kernel<<<(EDIM*TDIM)/1024, 256>>>(Wt, wth, EDIM*TDIM);
  conv_h_kernel<<<(EDIM*EDIM)/1024, 256>>>(Wa, wah, EDIM*EDIM);
  conv_h_kernel<<<(EDIM*2*EDIM)/1024, 256>>>(Wgt, wgth, EDIM*2*EDIM);
  conv_h_kernel<<<(EDIM*2*EDIM)/1024, 256>>>(Wga, wgah, EDIM*2*EDIM);
  convT_kernel<<<dim3(32,32), dim3(32,8)>>>(Wv, wvTh);
  cv_kernel<<<EDIM,128>>>(Wo, bv, bo, cv);

  GP z{};  // zero template

  // Wvo = Wo @ WvT (2-pass), grid (8,4,1)
  {
    GP p = z;
    p.A1h=woh; p.A1l=wol; p.lda1=EDIM; p.A2h=woh; p.A2l=wol; p.lda2=EDIM; p.K1=EDIM;
    p.Bh=wvTh; p.ldw=EDIM; p.bias=nullptr;
    p.outh=wvoh; p.outl=wvol; p.ldo=EDIM; p.Ktot=EDIM;
    gemm_kernel<false,true><<<dim3(8,4,1), 256, SM2>>>(p, p);
  }
  // merged projections: z0: t = text@Wt.T+bt (K=768), z1: a = audio@Wa.T+ba (K=1024)
  {
    GP p0 = z, p1 = z;
    p0.A1h=texh; p0.A1l=texl; p0.lda1=TDIM; p0.A2h=texh; p0.A2l=texl; p0.lda2=TDIM; p0.K1=TDIM;
    p0.Bh=wth; p0.ldw=TDIM; p0.bias=bt; p0.outh=th; p0.outl=tl; p0.ldo=EDIM; p0.Ktot=TDIM;
    p1.A1h=audh; p1.A1l=audl; p1.lda1=EDIM; p1.A2h=audh; p1.A2l=audl; p1.lda2=EDIM; p1.K1=EDIM;
    p1.Bh=wah; p1.ldw=EDIM; p1.bias=ba; p1.outh=ah; p1.outl=al; p1.ldo=EDIM; p1.Ktot=EDIM;
    gemm_kernel<false,true><<<dim3(8,BROWS/256,2), 256, SM2>>>(p0, p1);
  }
  // merged ctx: z0: tc = a@Wvo.T+cv, z1: ac = t@Wvo.T+cv
  {
    GP p0 = z, p1 = z;
    p0.A1h=ah; p0.A1l=al; p0.lda1=EDIM; p0.A2h=ah; p0.A2l=al; p0.lda2=EDIM; p0.K1=EDIM;
    p0.Bh=wvoh; p0.ldw=EDIM; p0.bias=cv; p0.outh=tch; p0.outl=tcl; p0.ldo=EDIM; p0.Ktot=EDIM;
    p1 = p0;
    p1.A1h=th; p1.A1l=tl; p1.A2h=th; p1.A2l=tl;
    p1.outh=ach; p1.outl=acl;
    gemm_kernel<false,true><<<dim3(8,BROWS/256,2), 256, SM2>>>(p0, p1);
  }
  // merged gates (single-pass): z0 refined_t, z1 refined_a
  {
    GP p0 = z, p1 = z;
    p0.A1h=th; p0.A1l=tl; p0.lda1=EDIM; p0.A2h=tch; p0.A2l=tcl; p0.lda2=EDIM; p0.K1=EDIM;
    p0.Bh=wgth; p0.ldw=2*EDIM; p0.bias=bgt;
    p0.gth=th; p0.gtl=tl; p0.gch=tch; p0.gcl=tcl;
    p0.outf=out; p0.ldo=EDIM; p0.Ktot=2*EDIM;
    p1.A1h=ah; p1.A1l=al; p1.lda1=EDIM; p1.A2h=ach; p1.A2l=acl; p1.lda2=EDIM; p1.K1=EDIM;
    p1.Bh=wgah; p1.ldw=2*EDIM; p1.bias=bga;
    p1.gth=ah; p1.gtl=al; p1.gch=ach; p1.gcl=acl;
    p1.outf=out + (size_t)BROWS*EDIM; p1.ldo=EDIM; p1.Ktot=2*EDIM;
    gemm_kernel<true,false><<<dim3(8,BROWS/256,2), 256, SM1>>>(p0, p1);
  }
}

// round 15
// speedup vs baseline: 2.4122x; 1.3044x over previous
#include <cuda_runtime.h>
#include <cuda_fp16.h>
#include <cstdint>

#define BROWS 16384
#define EDIM  1024
#define TDIM  768
#define NSTAGE 3
#define ROWB 80                        // padded smem row stride in bytes
#define A_BYTES 20480                  // 256 rows * 80
#define B_OFF   20480
#define STB     30720                  // stage bytes (A 20480 + B 10240)
#define SMEM_SZ (NSTAGE*STB)           // 92160

typedef __half f16;

// ---------------- static device scratch ----------------
__device__ f16 g_text_h[(size_t)BROWS*TDIM];
__device__ f16 g_aud_h [(size_t)BROWS*EDIM];
__device__ f16 g_t_h [(size_t)BROWS*EDIM], g_t_l [(size_t)BROWS*EDIM];
__device__ f16 g_a_h [(size_t)BROWS*EDIM], g_a_l [(size_t)BROWS*EDIM];
__device__ f16 g_tc_h[(size_t)BROWS*EDIM], g_tc_l[(size_t)BROWS*EDIM];
__device__ f16 g_ac_h[(size_t)BROWS*EDIM], g_ac_l[(size_t)BROWS*EDIM];
__device__ f16 g_wt_h [(size_t)EDIM*TDIM];
__device__ f16 g_wa_h [(size_t)EDIM*EDIM];
__device__ f16 g_wo_h [(size_t)EDIM*EDIM];
__device__ f16 g_wvT_h[(size_t)EDIM*EDIM];
__device__ f16 g_wvo_h[(size_t)EDIM*EDIM], g_wvo_l[(size_t)EDIM*EDIM];
__device__ f16 g_wgt_h[(size_t)EDIM*2*EDIM];
__device__ f16 g_wga_h[(size_t)EDIM*2*EDIM];
__device__ float g_cv[EDIM];

// ---------------- helpers ----------------
static __device__ __forceinline__ uint32_t s2u(const void* p){
  uint32_t a; asm("{ .reg .u64 t; cvta.to.shared.u64 t, %1; cvt.u32.u64 %0, t; }" : "=r"(a) : "l"(p)); return a;
}

#define LDM4(r, ad) asm volatile( \
  "ldmatrix.sync.aligned.m8n8.x4.shared.b16 {%0,%1,%2,%3}, [%4];" \
  : "=r"((r)[0]),"=r"((r)[1]),"=r"((r)[2]),"=r"((r)[3]) : "r"(ad))

#define MMA(cc, aa, b0, b1) asm volatile( \
  "mma.sync.aligned.m16n8k16.row.col.f32.f16.f16.f32 " \
  "{%0,%1,%2,%3},{%4,%5,%6,%7},{%8,%9},{%0,%1,%2,%3};" \
  : "+f"((cc)[0]),"+f"((cc)[1]),"+f"((cc)[2]),"+f"((cc)[3]) \
  : "r"((aa)[0]),"r"((aa)[1]),"r"((aa)[2]),"r"((aa)[3]),"r"(b0),"r"(b1))

#define CP16(dst, src) asm volatile( \
  "cp.async.cg.shared.global [%0], [%1], 16;" :: "r"(dst), "l"(src) : "memory")
#define CP_COMMIT() asm volatile("cp.async.commit_group;" ::: "memory")
#define CP_WAIT(n)  asm volatile("cp.async.wait_group %0;" :: "n"(n) : "memory")

// ---------------- merged conversion (7 segments, fp32 -> fp16 hi) ----------------
struct ConvTab {
  const float* src[7];
  f16* dst[7];
  int pre[8];         // prefix sums of vec4 counts
};
__global__ void conv_all_kernel(ConvTab tab){
  int i = blockIdx.x*blockDim.x + threadIdx.x;
  if (i >= tab.pre[7]) return;
  int s = 0;
  #pragma unroll
  for (int k=1;k<7;k++) if (i >= tab.pre[k]) s = k;
  int local = i - tab.pre[s];
  float4 v = ((const float4*)tab.src[s])[local];
  uint2 ph;
  ph.x=(uint32_t)__half_as_ushort(__float2half_rn(v.x))|((uint32_t)__half_as_ushort(__float2half_rn(v.y))<<16);
  ph.y=(uint32_t)__half_as_ushort(__float2half_rn(v.z))|((uint32_t)__half_as_ushort(__float2half_rn(v.w))<<16);
  ((uint2*)tab.dst[s])[local] = ph;
}

// dst[n][k] = src[k][n], EDIM x EDIM, hi only
__global__ void convT_kernel(const float* __restrict__ src, f16* __restrict__ hi){
  __shared__ float tile[32][33];
  int k0 = blockIdx.y*32, n0 = blockIdx.x*32;
  int tx = threadIdx.x, ty = threadIdx.y;      // 32 x 8
  #pragma unroll
  for (int j=0;j<4;j++)
    tile[ty+j*8][tx] = src[(size_t)(k0+ty+j*8)*EDIM + n0+tx];
  __syncthreads();
  #pragma unroll
  for (int j=0;j<4;j++){
    float v = tile[tx][ty+j*8];
    hi[(size_t)(n0+ty+j*8)*EDIM + k0+tx] = __float2half_rn(v);
  }
}
__global__ void cv_kernel(const float* __restrict__ Wo, const float* __restrict__ bv,
                          const float* __restrict__ bo, float* __restrict__ cv){
  __shared__ float red[128];
  int i = blockIdx.x;
  float s = 0.f;
  for (int k = threadIdx.x; k < EDIM; k += 128) s += Wo[(size_t)i*EDIM + k] * bv[k];
  red[threadIdx.x] = s; __syncthreads();
  for (int off = 64; off; off >>= 1){
    if (threadIdx.x < off) red[threadIdx.x] += red[threadIdx.x+off];
    __syncthreads();
  }
  if (threadIdx.x == 0) cv[i] = red[0] + bo[i];
}

// ---------------- GEMM params ----------------
struct GP {
  const f16 *A1h; int lda1;
  const f16 *A2h; int lda2; int K1;
  const f16 *Bh; int ldw;
  const float* bias;
  const f16 *gth, *gtl, *gch, *gcl;
  float* outf; f16 *outh, *outl;
  int ldo; int Ktot; int ylim;
};

// C[m][n] = sum_k Ah[m][k]*Bh[n][k] + bias. Single-pass fp16, fp32 accum.
// GATE: sigmoid-blend epilogue -> fp32 out; else fp16 hi/lo outputs.
// CTA tile 256x128, K-chunk 32, 8 warps 4x2, warp tile 64x64, 3-stage cp.async.
// blockIdx.z selects one of three param structs; blockIdx.y >= ylim exits early.
template<bool GATE>
__global__ void __launch_bounds__(256)
gemm_kernel(GP p0, GP p1, GP p2)
{
  const GP p = (blockIdx.z == 0) ? p0 : ((blockIdx.z == 1) ? p1 : p2);
  if ((int)blockIdx.y >= p.ylim) return;

  extern __shared__ char smem[];
  const int tid = threadIdx.x, lane = tid & 31, wid = tid >> 5;
  const int mwarp = wid & 3, nwarp = wid >> 2;           // 4 x 2 warp grid
  const int m0 = blockIdx.y * 256, n0 = blockIdx.x * 128;
  const uint32_t sb = s2u(smem);

  float c[4][8][4];
  #pragma unroll
  for (int i=0;i<4;i++)
    #pragma unroll
    for (int j=0;j<8;j++)
      #pragma unroll
      for (int q=0;q<4;q++) c[i][j][q] = 0.f;

  const uint32_t aoff = (uint32_t)((lane&15)*ROWB + ((lane>>4)&1)*16);
  const uint32_t boff = (uint32_t)(((lane&7) + ((lane>>4)&1)*8)*ROWB + ((lane>>3)&1)*16);

  const int nk = p.Ktot >> 5;

  #define ISSUE(kc) do { \
    int kk = (kc) << 5; \
    uint32_t st = sb + (uint32_t)((kc)%NSTAGE)*STB; \
    const f16 *ah_; int lda_; \
    if (kk < p.K1){ ah_ = p.A1h + (size_t)m0*p.lda1 + kk; lda_ = p.lda1; } \
    else          { ah_ = p.A2h + (size_t)m0*p.lda2 + (kk-p.K1); lda_ = p.lda2; } \
    _Pragma("unroll") \
    for (int i=0;i<4;i++){ \
      int e = tid + i*256; int row = e>>2, seg = e&3; \
      CP16(st + (uint32_t)(row*ROWB + seg*16), ah_ + (size_t)row*lda_ + seg*8); \
    } \
    _Pragma("unroll") \
    for (int i=0;i<2;i++){ \
      int e = tid + i*256; int row = e>>2, seg = e&3; \
      CP16(st + B_OFF + (uint32_t)(row*ROWB + seg*16), p.Bh + (size_t)(n0+row)*p.ldw + kk + seg*8); \
    } \
    CP_COMMIT(); \
  } while(0)

  ISSUE(0); ISSUE(1); ISSUE(2);

  for (int kc = 0; kc < nk; kc++){
    CP_WAIT(2);
    __syncthreads();
    {
      const uint32_t base = sb + (uint32_t)(kc%NSTAGE)*STB;
      #pragma unroll
      for (int ks=0; ks<2; ks++){
        uint32_t ah[4][4], bb[4][4];
        #pragma unroll
        for (int mi=0;mi<4;mi++){
          uint32_t ad = base + (uint32_t)((mwarp*64 + mi*16)*ROWB + ks*32) + aoff;
          LDM4(ah[mi], ad);
        }
        #pragma unroll
        for (int bi=0;bi<4;bi++){
          uint32_t bd = base + B_OFF + (uint32_t)((nwarp*64 + bi*16)*ROWB + ks*32) + boff;
          LDM4(bb[bi], bd);
        }
        #pragma unroll
        for (int mi=0;mi<4;mi++)
          #pragma unroll
          for (int ni=0;ni<8;ni++)
            MMA(c[mi][ni], ah[mi], bb[ni>>1][(ni&1)*2], bb[ni>>1][(ni&1)*2+1]);
      }
    }
    __syncthreads();
    if (kc+3 < nk) ISSUE(kc+3); else CP_COMMIT();
  }
  #undef ISSUE

  // ---- epilogue ----
  const int gid = lane >> 2, tig = lane & 3;
  #pragma unroll
  for (int mi=0;mi<4;mi++){
    const int rbase = m0 + mwarp*64 + mi*16 + gid;
    #pragma unroll
    for (int ni=0;ni<8;ni++){
      const int col = n0 + nwarp*64 + ni*8 + tig*2;
      const float b0 = p.bias ? p.bias[col] : 0.f;
      const float b1 = p.bias ? p.bias[col+1] : 0.f;
      #pragma unroll
      for (int half_=0; half_<2; half_++){
        const int r = rbase + half_*8;
        float z0 = c[mi][ni][half_*2+0] + b0;
        float z1 = c[mi][ni][half_*2+1] + b1;
        if (GATE){
          __half2 th = *(const __half2*)(p.gth + (size_t)r*EDIM + col);
          __half2 tl = *(const __half2*)(p.gtl + (size_t)r*EDIM + col);
          __half2 ch = *(const __half2*)(p.gch + (size_t)r*EDIM + col);
          __half2 cl = *(const __half2*)(p.gcl + (size_t)r*EDIM + col);
          float tv0 = __half2float(th.x)+__half2float(tl.x);
          float tv1 = __half2float(th.y)+__half2float(tl.y);
          float cv0 = __half2float(ch.x)+__half2float(cl.x);
          float cv1 = __half2float(ch.y)+__half2float(cl.y);
          float g0 = 1.f/(1.f + __expf(-z0));
          float g1 = 1.f/(1.f + __expf(-z1));
          float2 o; o.x = g0*tv0 + (1.f-g0)*cv0; o.y = g1*tv1 + (1.f-g1)*cv1;
          *(float2*)(p.outf + (size_t)r*p.ldo + col) = o;
        } else {
          f16 h0=__float2half_rn(z0), h1=__float2half_rn(z1);
          f16 l0=__float2half_rn(z0-__half2float(h0));
          f16 l1=__float2half_rn(z1-__half2float(h1));
          uint32_t ph = (uint32_t)__half_as_ushort(h0)|((uint32_t)__half_as_ushort(h1)<<16);
          uint32_t pl = (uint32_t)__half_as_ushort(l0)|((uint32_t)__half_as_ushort(l1)<<16);
          *(uint32_t*)(p.outh + (size_t)r*p.ldo + col) = ph;
          *(uint32_t*)(p.outl + (size_t)r*p.ldo + col) = pl;
        }
      }
    }
  }
}

extern "C" void kernel_launch(void* const* d_in, const int* in_sizes, int n_in,
                              void* d_out, int out_size){
  const float* text = (const float*)d_in[0];
  const float* audio= (const float*)d_in[1];
  const float* Wt = (const float*)d_in[2];  const float* bt = (const float*)d_in[3];
  const float* Wa = (const float*)d_in[4];  const float* ba = (const float*)d_in[5];
  const float* Wv = (const float*)d_in[10]; const float* bv = (const float*)d_in[11];
  const float* Wo = (const float*)d_in[12]; const float* bo = (const float*)d_in[13];
  const float* Wgt= (const float*)d_in[14]; const float* bgt= (const float*)d_in[15];
  const float* Wga= (const float*)d_in[16]; const float* bga= (const float*)d_in[17];
  float* out = (float*)d_out;

  f16 *texh,*audh,*th,*tl,*ah,*al,*tch,*tcl,*ach,*acl;
  f16 *wth,*wah,*woh,*wvTh,*wvoh,*wvol,*wgth,*wgah;
  float *cv;
  cudaGetSymbolAddress((void**)&texh, g_text_h);
  cudaGetSymbolAddress((void**)&audh, g_aud_h);
  cudaGetSymbolAddress((void**)&th, g_t_h);   cudaGetSymbolAddress((void**)&tl, g_t_l);
  cudaGetSymbolAddress((void**)&ah, g_a_h);   cudaGetSymbolAddress((void**)&al, g_a_l);
  cudaGetSymbolAddress((void**)&tch, g_tc_h); cudaGetSymbolAddress((void**)&tcl, g_tc_l);
  cudaGetSymbolAddress((void**)&ach, g_ac_h); cudaGetSymbolAddress((void**)&acl, g_ac_l);
  cudaGetSymbolAddress((void**)&wth, g_wt_h);
  cudaGetSymbolAddress((void**)&wah, g_wa_h);
  cudaGetSymbolAddress((void**)&woh, g_wo_h);
  cudaGetSymbolAddress((void**)&wvTh, g_wvT_h);
  cudaGetSymbolAddress((void**)&wvoh, g_wvo_h); cudaGetSymbolAddress((void**)&wvol, g_wvo_l);
  cudaGetSymbolAddress((void**)&wgth, g_wgt_h);
  cudaGetSymbolAddress((void**)&wgah, g_wga_h);
  cudaGetSymbolAddress((void**)&cv, g_cv);

  cudaFuncSetAttribute(gemm_kernel<false>, cudaFuncAttributeMaxDynamicSharedMemorySize, SMEM_SZ);
  cudaFuncSetAttribute(gemm_kernel<true >, cudaFuncAttributeMaxDynamicSharedMemorySize, SMEM_SZ);

  // ---- merged conversion (single launch) ----
  {
    ConvTab tab;
    const float* srcs[7] = {text, audio, Wt, Wa, Wo, Wgt, Wga};
    f16* dsts[7] = {texh, audh, wth, wah, woh, wgth, wgah};
    int n4[7] = {BROWS*TDIM/4, BROWS*EDIM/4, EDIM*TDIM/4, EDIM*EDIM/4,
                 EDIM*EDIM/4, EDIM*2*EDIM/4, EDIM*2*EDIM/4};
    int pre = 0;
    for (int i=0;i<7;i++){ tab.src[i]=srcs[i]; tab.dst[i]=dsts[i]; tab.pre[i]=pre; pre+=n4[i]; }
    tab.pre[7] = pre;
    conv_all_kernel<<<(pre+255)/256, 256>>>(tab);
  }
  convT_kernel<<<dim3(32,32), dim3(32,8)>>>(Wv, wvTh);
  cv_kernel<<<EDIM,128>>>(Wo, bv, bo, cv);

  GP z{};  // zero template (ylim=0 -> inert)

  // merged launch 1: z0 t=text@Wt.T+bt, z1 a=audio@Wa.T+ba, z2 Wvo=Wo@WvT (ylim 4)
  {
    GP p0 = z, p1 = z, p2 = z;
    p0.A1h=texh; p0.lda1=TDIM; p0.A2h=texh; p0.lda2=TDIM; p0.K1=TDIM;
    p0.Bh=wth; p0.ldw=TDIM; p0.bias=bt; p0.outh=th; p0.outl=tl; p0.ldo=EDIM; p0.Ktot=TDIM; p0.ylim=BROWS/256;
    p1.A1h=audh; p1.lda1=EDIM; p1.A2h=audh; p1.lda2=EDIM; p1.K1=EDIM;
    p1.Bh=wah; p1.ldw=EDIM; p1.bias=ba; p1.outh=ah; p1.outl=al; p1.ldo=EDIM; p1.Ktot=EDIM; p1.ylim=BROWS/256;
    p2.A1h=woh; p2.lda1=EDIM; p2.A2h=woh; p2.lda2=EDIM; p2.K1=EDIM;
    p2.Bh=wvTh; p2.ldw=EDIM; p2.bias=nullptr; p2.outh=wvoh; p2.outl=wvol; p2.ldo=EDIM; p2.Ktot=EDIM; p2.ylim=4;
    gemm_kernel<false><<<dim3(8,BROWS/256,3), 256, SMEM_SZ>>>(p0, p1, p2);
  }
  // merged launch 2: z0 tc = a@Wvo.T+cv, z1 ac = t@Wvo.T+cv
  {
    GP p0 = z, p1 = z;
    p0.A1h=ah; p0.lda1=EDIM; p0.A2h=ah; p0.lda2=EDIM; p0.K1=EDIM;
    p0.Bh=wvoh; p0.ldw=EDIM; p0.bias=cv; p0.outh=tch; p0.outl=tcl; p0.ldo=EDIM; p0.Ktot=EDIM; p0.ylim=BROWS/256;
    p1 = p0; p1.A1h=th; p1.A2h=th; p1.outh=ach; p1.outl=acl;
    gemm_kernel<false><<<dim3(8,BROWS/256,2), 256, SMEM_SZ>>>(p0, p1, z);
  }
  // merged launch 3 (gates): z0 refined_t, z1 refined_a
  {
    GP p0 = z, p1 = z;
    p0.A1h=th; p0.lda1=EDIM; p0.A2h=tch; p0.lda2=EDIM; p0.K1=EDIM;
    p0.Bh=wgth; p0.ldw=2*EDIM; p0.bias=bgt;
    p0.gth=th; p0.gtl=tl; p0.gch=tch; p0.gcl=tcl;
    p0.outf=out; p0.ldo=EDIM; p0.Ktot=2*EDIM; p0.ylim=BROWS/256;
    p1.A1h=ah; p1.lda1=EDIM; p1.A2h=ach; p1.lda2=EDIM; p1.K1=EDIM;
    p1.Bh=wgah; p1.ldw=2*EDIM; p1.bias=bga;
    p1.gth=ah; p1.gtl=al; p1.gch=ach; p1.gcl=acl;
    p1.outf=out + (size_t)BROWS*EDIM; p1.ldo=EDIM; p1.Ktot=2*EDIM; p1.ylim=BROWS/256;
    gemm_kernel<true><<<dim3(8,BROWS/256,2), 256, SMEM_SZ>>>(p0, p1, z);
  }
}